// round 4
// baseline (speedup 1.0000x reference)
#include <cuda_runtime.h>
#include <cuda_bf16.h>
#include <math.h>

// Problem constants
#define BB 256
#define TT 512
#define DD 512
#define HH 256
#define KK 3
#define MM (BB * TT)   // 131072 rows

// Scratch
__device__ float g_em[TT * KK * BB];     // layout [t][k][b]  (coalesced for CRF)
__device__ int   g_tagsT[TT * BB];       // layout [t][b]

// ---------------------------------------------------------------------------
// helpers
// ---------------------------------------------------------------------------
__device__ __forceinline__ void mma_tf32(float (&d)[4],
                                         const unsigned (&a)[4],
                                         const unsigned (&b)[2]) {
    asm volatile(
        "mma.sync.aligned.m16n8k8.row.col.f32.tf32.tf32.f32 "
        "{%0,%1,%2,%3}, {%4,%5,%6,%7}, {%8,%9}, {%0,%1,%2,%3};\n"
        : "+f"(d[0]), "+f"(d[1]), "+f"(d[2]), "+f"(d[3])
        : "r"(a[0]), "r"(a[1]), "r"(a[2]), "r"(a[3]),
          "r"(b[0]), "r"(b[1]));
}

#define CP_ASYNC16(dst, src) \
    asm volatile("cp.async.cg.shared.global [%0], [%1], 16;\n" :: "r"(dst), "l"(src))
#define CP_COMMIT() asm volatile("cp.async.commit_group;\n")
#define CP_WAIT(n)  asm volatile("cp.async.wait_group %0;\n" :: "n"(n))

// Dynamic smem layout: 3 stages of {x tile 64x20, W1 tile 16x264}
#define SX_STRIDE (64 * 20)       // 1280 floats / stage
#define SW_STRIDE (16 * 264)      // 4224 floats / stage
#define DYN_SMEM_BYTES (3 * (SX_STRIDE + SW_STRIDE) * 4)   // 66048

// ---------------------------------------------------------------------------
// Kernel 1: fused  em = gelu(x @ W1 + b1) @ W2 + b2   via tf32 tensor cores
// Block: 256 thr (8 warps). BM=64 rows, BN=256 (full H), BK=16.
// 3-stage cp.async pipeline, ONE __syncthreads per k-iter.
// Raw f32 bits fed to mma.tf32 (HW truncation) -> no cvt instructions.
// ---------------------------------------------------------------------------
__global__ __launch_bounds__(256, 2)
void fused_mlp_tc(const float* __restrict__ x,
                  const float* __restrict__ W1,
                  const float* __restrict__ b1,
                  const float* __restrict__ W2,
                  const float* __restrict__ b2)
{
    extern __shared__ float dsm[];
    float* s_x = dsm;                        // [3][64][20]
    float* s_w = dsm + 3 * SX_STRIDE;        // [3][16][264]

    __shared__ float s_w2[256][3];
    __shared__ float s_b1[256];
    __shared__ float em_s[64][3];

    const int tid  = threadIdx.x;
    const int wid  = tid >> 5;
    const int lane = tid & 31;
    const int g    = lane >> 2;   // row-in-8
    const int c    = lane & 3;    // k / col-pair selector
    const int row_base = blockIdx.x * 64;
    const int cw   = wid * 32;    // warp's column base in H

    s_b1[tid]    = b1[tid];
    s_w2[tid][0] = W2[tid * 3 + 0];
    s_w2[tid][1] = W2[tid * 3 + 1];
    s_w2[tid][2] = W2[tid * 3 + 2];
    if (tid < 192) ((float*)em_s)[tid] = 0.0f;

    float acc[4][4][4];
    #pragma unroll
    for (int mt = 0; mt < 4; ++mt)
        #pragma unroll
        for (int nt = 0; nt < 4; ++nt)
            #pragma unroll
            for (int e = 0; e < 4; ++e) acc[mt][nt][e] = 0.0f;

    // ---- async tile loader ----
    const int xr = tid >> 2;            // 0..63
    const int xq = (tid & 3) << 2;      // 0,4,8,12
    auto issue_stage = [&](int s, int k0) {
        unsigned dx = (unsigned)__cvta_generic_to_shared(
            &s_x[s * SX_STRIDE + xr * 20 + xq]);
        CP_ASYNC16(dx, &x[(size_t)(row_base + xr) * DD + k0 + xq]);
        #pragma unroll
        for (int p = 0; p < 4; ++p) {
            const int chunk = tid + p * 256;      // 0..1023
            const int kr = chunk >> 6;            // 0..15
            const int c4 = (chunk & 63) << 2;     // 0..252
            unsigned dw = (unsigned)__cvta_generic_to_shared(
                &s_w[s * SW_STRIDE + kr * 264 + c4]);
            CP_ASYNC16(dw, &W1[(size_t)(k0 + kr) * HH + c4]);
        }
        CP_COMMIT();
    };

    issue_stage(0, 0);
    issue_stage(1, 16);

    const int NITER = DD / 16;  // 32
    int cur = 0;                // stage to compute
    int wr  = 2;                // stage to fill this iter

    #pragma unroll 1
    for (int it = 0; it < NITER; ++it) {
        // wait for stage `cur` (groups retire FIFO)
        if (it == NITER - 1) { CP_WAIT(0); }
        else                 { CP_WAIT(1); }
        __syncthreads();   // all warps done with stage `wr` (read at it-1) + see `cur`

        if (it + 2 < NITER) issue_stage(wr, (it + 2) * 16);

        const float* xb = &s_x[cur * SX_STRIDE];
        const float* wb = &s_w[cur * SW_STRIDE];

        #pragma unroll
        for (int ks = 0; ks < 2; ++ks) {
            const int kk = ks * 8;
            unsigned bf[4][2];
            #pragma unroll
            for (int nt = 0; nt < 4; ++nt) {
                const int n = cw + nt * 8 + g;
                bf[nt][0] = __float_as_uint(wb[(kk + c) * 264 + n]);
                bf[nt][1] = __float_as_uint(wb[(kk + c + 4) * 264 + n]);
            }
            #pragma unroll
            for (int mt = 0; mt < 4; ++mt) {
                const int r0 = mt * 16 + g;
                unsigned af[4];
                af[0] = __float_as_uint(xb[r0 * 20 + kk + c]);
                af[1] = __float_as_uint(xb[(r0 + 8) * 20 + kk + c]);
                af[2] = __float_as_uint(xb[r0 * 20 + kk + c + 4]);
                af[3] = __float_as_uint(xb[(r0 + 8) * 20 + kk + c + 4]);
                #pragma unroll
                for (int nt = 0; nt < 4; ++nt)
                    mma_tf32(acc[mt][nt], af, bf[nt]);
            }
        }

        cur = (cur == 2) ? 0 : cur + 1;
        wr  = (wr  == 2) ? 0 : wr  + 1;
    }

    // ---- epilogue: bias + exact gelu + W2 contraction ----
    float pem[8][3];   // row slots: (mt, upper/lower) -> rows mt*16+g, mt*16+g+8
    #pragma unroll
    for (int i = 0; i < 8; ++i)
        #pragma unroll
        for (int k = 0; k < 3; ++k) pem[i][k] = 0.0f;

    #pragma unroll
    for (int mt = 0; mt < 4; ++mt)
        #pragma unroll
        for (int nt = 0; nt < 4; ++nt)
            #pragma unroll
            for (int e = 0; e < 4; ++e) {
                const int col = cw + nt * 8 + 2 * c + (e & 1);
                const int slot = mt * 2 + (e >> 1);
                const float v = acc[mt][nt][e] + s_b1[col];
                const float h = 0.5f * v * (1.0f + erff(v * 0.7071067811865476f));
                pem[slot][0] = fmaf(h, s_w2[col][0], pem[slot][0]);
                pem[slot][1] = fmaf(h, s_w2[col][1], pem[slot][1]);
                pem[slot][2] = fmaf(h, s_w2[col][2], pem[slot][2]);
            }

    // reduce across the 4 lanes sharing a row
    #pragma unroll
    for (int d = 1; d < 4; d <<= 1)
        #pragma unroll
        for (int i = 0; i < 8; ++i)
            #pragma unroll
            for (int k = 0; k < 3; ++k)
                pem[i][k] += __shfl_xor_sync(0xffffffffu, pem[i][k], d);

    if (c == 0) {
        #pragma unroll
        for (int i = 0; i < 8; ++i) {
            const int row = (i >> 1) * 16 + g + (i & 1) * 8;
            atomicAdd(&em_s[row][0], pem[i][0]);
            atomicAdd(&em_s[row][1], pem[i][1]);
            atomicAdd(&em_s[row][2], pem[i][2]);
        }
    }
    __syncthreads();

    if (tid < 192) {
        const int r = tid / 3, k = tid % 3;
        const int m = row_base + r;
        const int b = m >> 9;          // m / 512
        const int t = m & 511;
        g_em[((size_t)t * 3 + k) * BB + b] = em_s[r][k] + b2[k];
    }
}

// ---------------------------------------------------------------------------
// tags transpose: [b][t] -> [t][b]  (+ zero-init the output scalar)
// ---------------------------------------------------------------------------
__global__ void transpose_tags_kernel(const int* __restrict__ tags, float* out) {
    __shared__ int tile[32][33];
    if (blockIdx.x == 0 && blockIdx.y == 0 && threadIdx.x == 0 && threadIdx.y == 0)
        out[0] = 0.0f;
    const int t0 = blockIdx.x * 32;
    const int b0 = blockIdx.y * 32;
    tile[threadIdx.y][threadIdx.x] = tags[(size_t)(b0 + threadIdx.y) * TT + t0 + threadIdx.x];
    __syncthreads();
    g_tagsT[(size_t)(t0 + threadIdx.y) * BB + b0 + threadIdx.x] =
        tile[threadIdx.x][threadIdx.y];
}

// ---------------------------------------------------------------------------
// Kernel 2: CRF. One thread per batch; coalesced [t][k][b] reads,
// double-buffered 8-step chunks so loads of chunk j+1 overlap compute of j.
// ---------------------------------------------------------------------------
__device__ __forceinline__ float sel3(float a, float b, float c, int i) {
    return (i == 0) ? a : ((i == 1) ? b : c);
}
__device__ __forceinline__ float lse3(float x, float y, float z) {
    const float m = fmaxf(fmaxf(x, y), z);
    return m + __logf(__expf(x - m) + __expf(y - m) + __expf(z - m));
}

__global__ void crf_kernel(const int* __restrict__ lengths,
                           const float* __restrict__ trans,
                           const float* __restrict__ start,
                           const float* __restrict__ end,
                           float* __restrict__ out)
{
    const int b = blockIdx.x * 32 + threadIdx.x;   // 0..255

    const float t00 = trans[0], t01 = trans[1], t02 = trans[2];
    const float t10 = trans[3], t11 = trans[4], t12 = trans[5];
    const float t20 = trans[6], t21 = trans[7], t22 = trans[8];
    const float st0 = start[0], st1 = start[1], st2 = start[2];
    const float en0 = end[0],   en1 = end[1],   en2 = end[2];

    const int len = max(lengths[b], 1);

    float e0 = g_em[0 * BB + b];
    float e1 = g_em[1 * BB + b];
    float e2 = g_em[2 * BB + b];
    int tp = g_tagsT[b];
    float num = sel3(st0, st1, st2, tp) + sel3(e0, e1, e2, tp);
    float a0 = st0 + e0, a1 = st1 + e1, a2 = st2 + e2;

    float ec[2][8][3];
    int   tc[2][8];

    auto load_chunk = [&](int buf, int base) {
        #pragma unroll
        for (int j = 0; j < 8; ++j) {
            const int t = base + j;
            if (t < TT) {
                ec[buf][j][0] = g_em[((size_t)t * 3 + 0) * BB + b];
                ec[buf][j][1] = g_em[((size_t)t * 3 + 1) * BB + b];
                ec[buf][j][2] = g_em[((size_t)t * 3 + 2) * BB + b];
                tc[buf][j]    = g_tagsT[(size_t)t * BB + b];
            }
        }
    };

    load_chunk(0, 1);
    int cur = 0;

    #pragma unroll 1
    for (int t0 = 1; t0 < len; t0 += 8) {
        if (t0 + 8 < len) load_chunk(cur ^ 1, t0 + 8);

        #pragma unroll
        for (int j = 0; j < 8; ++j) {
            const int t = t0 + j;
            if (t >= len) break;
            e0 = ec[cur][j][0]; e1 = ec[cur][j][1]; e2 = ec[cur][j][2];
            const float n0 = lse3(a0 + t00, a1 + t10, a2 + t20) + e0;
            const float n1 = lse3(a0 + t01, a1 + t11, a2 + t21) + e1;
            const float n2 = lse3(a0 + t02, a1 + t12, a2 + t22) + e2;
            a0 = n0; a1 = n1; a2 = n2;

            const int tcur = tc[cur][j];
            const float trv =
                (tp == 0) ? sel3(t00, t01, t02, tcur)
              : (tp == 1) ? sel3(t10, t11, t12, tcur)
                          : sel3(t20, t21, t22, tcur);
            num += trv + sel3(e0, e1, e2, tcur);
            tp = tcur;
        }
        cur ^= 1;
    }
    num += sel3(en0, en1, en2, tp);
    const float denom = lse3(a0 + en0, a1 + en1, a2 + en2);

    float llh = num - denom;
    #pragma unroll
    for (int off = 16; off > 0; off >>= 1)
        llh += __shfl_xor_sync(0xffffffffu, llh, off);
    if (threadIdx.x == 0)
        atomicAdd(out, -llh * (1.0f / (float)BB));
}

// ---------------------------------------------------------------------------
extern "C" void kernel_launch(void* const* d_in, const int* in_sizes, int n_in,
                              void* d_out, int out_size)
{
    const float* x       = (const float*)d_in[0];
    const int*   tags    = (const int*)  d_in[1];
    const int*   lengths = (const int*)  d_in[2];
    const float* W1      = (const float*)d_in[3];
    const float* b1      = (const float*)d_in[4];
    const float* W2      = (const float*)d_in[5];
    const float* b2      = (const float*)d_in[6];
    const float* trans   = (const float*)d_in[7];
    const float* start   = (const float*)d_in[8];
    const float* end     = (const float*)d_in[9];

    cudaFuncSetAttribute(fused_mlp_tc,
                         cudaFuncAttributeMaxDynamicSharedMemorySize,
                         DYN_SMEM_BYTES);

    fused_mlp_tc<<<MM / 64, 256, DYN_SMEM_BYTES>>>(x, W1, b1, W2, b2);
    transpose_tags_kernel<<<dim3(TT / 32, BB / 32), dim3(32, 32)>>>(tags, (float*)d_out);
    crf_kernel<<<8, 32>>>(lengths, trans, start, end, (float*)d_out);
}

// round 5
// speedup vs baseline: 1.2452x; 1.2452x over previous
#include <cuda_runtime.h>
#include <cuda_bf16.h>
#include <math.h>

// Problem constants
#define BB 256
#define TT 512
#define DD 512
#define HH 256
#define KK 3
#define MM (BB * TT)   // 131072 rows

// Scratch
__device__ float g_em[TT * KK * BB];     // layout [t][k][b]  (coalesced for CRF)
__device__ int   g_tagsT[TT * BB];       // layout [t][b]

// ---------------------------------------------------------------------------
// helpers
// ---------------------------------------------------------------------------
__device__ __forceinline__ void mma_tf32(float (&d)[4],
                                         const unsigned (&a)[4],
                                         const unsigned (&b)[2]) {
    asm volatile(
        "mma.sync.aligned.m16n8k8.row.col.f32.tf32.tf32.f32 "
        "{%0,%1,%2,%3}, {%4,%5,%6,%7}, {%8,%9}, {%0,%1,%2,%3};\n"
        : "+f"(d[0]), "+f"(d[1]), "+f"(d[2]), "+f"(d[3])
        : "r"(a[0]), "r"(a[1]), "r"(a[2]), "r"(a[3]),
          "r"(b[0]), "r"(b[1]));
}

#define CP_ASYNC16(dst, src) \
    asm volatile("cp.async.cg.shared.global [%0], [%1], 16;\n" :: "r"(dst), "l"(src))
#define CP_COMMIT() asm volatile("cp.async.commit_group;\n")
#define CP_WAIT(n)  asm volatile("cp.async.wait_group %0;\n" :: "n"(n))

// Dynamic smem layout: 3 stages of {x tile 64x20, W1 tile 16x264}
#define SX_STRIDE (64 * 20)       // 1280 floats / stage
#define SW_STRIDE (16 * 264)      // 4224 floats / stage
#define DYN_SMEM_BYTES (3 * (SX_STRIDE + SW_STRIDE) * 4)   // 66048

// ---------------------------------------------------------------------------
// Kernel 1: fused  em = gelu(x @ W1 + b1) @ W2 + b2   via tf32 tensor cores
// (unchanged from R4 — proven: 274us, tensor pipe 44.7%)
// ---------------------------------------------------------------------------
__global__ __launch_bounds__(256, 2)
void fused_mlp_tc(const float* __restrict__ x,
                  const float* __restrict__ W1,
                  const float* __restrict__ b1,
                  const float* __restrict__ W2,
                  const float* __restrict__ b2)
{
    extern __shared__ float dsm[];
    float* s_x = dsm;                        // [3][64][20]
    float* s_w = dsm + 3 * SX_STRIDE;        // [3][16][264]

    __shared__ float s_w2[256][3];
    __shared__ float s_b1[256];
    __shared__ float em_s[64][3];

    const int tid  = threadIdx.x;
    const int wid  = tid >> 5;
    const int lane = tid & 31;
    const int g    = lane >> 2;   // row-in-8
    const int c    = lane & 3;    // k / col-pair selector
    const int row_base = blockIdx.x * 64;
    const int cw   = wid * 32;    // warp's column base in H

    s_b1[tid]    = b1[tid];
    s_w2[tid][0] = W2[tid * 3 + 0];
    s_w2[tid][1] = W2[tid * 3 + 1];
    s_w2[tid][2] = W2[tid * 3 + 2];
    if (tid < 192) ((float*)em_s)[tid] = 0.0f;

    float acc[4][4][4];
    #pragma unroll
    for (int mt = 0; mt < 4; ++mt)
        #pragma unroll
        for (int nt = 0; nt < 4; ++nt)
            #pragma unroll
            for (int e = 0; e < 4; ++e) acc[mt][nt][e] = 0.0f;

    // ---- async tile loader ----
    const int xr = tid >> 2;            // 0..63
    const int xq = (tid & 3) << 2;      // 0,4,8,12
    auto issue_stage = [&](int s, int k0) {
        unsigned dx = (unsigned)__cvta_generic_to_shared(
            &s_x[s * SX_STRIDE + xr * 20 + xq]);
        CP_ASYNC16(dx, &x[(size_t)(row_base + xr) * DD + k0 + xq]);
        #pragma unroll
        for (int p = 0; p < 4; ++p) {
            const int chunk = tid + p * 256;      // 0..1023
            const int kr = chunk >> 6;            // 0..15
            const int c4 = (chunk & 63) << 2;     // 0..252
            unsigned dw = (unsigned)__cvta_generic_to_shared(
                &s_w[s * SW_STRIDE + kr * 264 + c4]);
            CP_ASYNC16(dw, &W1[(size_t)(k0 + kr) * HH + c4]);
        }
        CP_COMMIT();
    };

    issue_stage(0, 0);
    issue_stage(1, 16);

    const int NITER = DD / 16;  // 32
    int cur = 0;                // stage to compute
    int wr  = 2;                // stage to fill this iter

    #pragma unroll 1
    for (int it = 0; it < NITER; ++it) {
        if (it == NITER - 1) { CP_WAIT(0); }
        else                 { CP_WAIT(1); }
        __syncthreads();

        if (it + 2 < NITER) issue_stage(wr, (it + 2) * 16);

        const float* xb = &s_x[cur * SX_STRIDE];
        const float* wb = &s_w[cur * SW_STRIDE];

        #pragma unroll
        for (int ks = 0; ks < 2; ++ks) {
            const int kk = ks * 8;
            unsigned bf[4][2];
            #pragma unroll
            for (int nt = 0; nt < 4; ++nt) {
                const int n = cw + nt * 8 + g;
                bf[nt][0] = __float_as_uint(wb[(kk + c) * 264 + n]);
                bf[nt][1] = __float_as_uint(wb[(kk + c + 4) * 264 + n]);
            }
            #pragma unroll
            for (int mt = 0; mt < 4; ++mt) {
                const int r0 = mt * 16 + g;
                unsigned af[4];
                af[0] = __float_as_uint(xb[r0 * 20 + kk + c]);
                af[1] = __float_as_uint(xb[(r0 + 8) * 20 + kk + c]);
                af[2] = __float_as_uint(xb[r0 * 20 + kk + c + 4]);
                af[3] = __float_as_uint(xb[(r0 + 8) * 20 + kk + c + 4]);
                #pragma unroll
                for (int nt = 0; nt < 4; ++nt)
                    mma_tf32(acc[mt][nt], af, bf[nt]);
            }
        }

        cur = (cur == 2) ? 0 : cur + 1;
        wr  = (wr  == 2) ? 0 : wr  + 1;
    }

    // ---- epilogue: bias + exact gelu + W2 contraction ----
    float pem[8][3];
    #pragma unroll
    for (int i = 0; i < 8; ++i)
        #pragma unroll
        for (int k = 0; k < 3; ++k) pem[i][k] = 0.0f;

    #pragma unroll
    for (int mt = 0; mt < 4; ++mt)
        #pragma unroll
        for (int nt = 0; nt < 4; ++nt)
            #pragma unroll
            for (int e = 0; e < 4; ++e) {
                const int col = cw + nt * 8 + 2 * c + (e & 1);
                const int slot = mt * 2 + (e >> 1);
                const float v = acc[mt][nt][e] + s_b1[col];
                const float h = 0.5f * v * (1.0f + erff(v * 0.7071067811865476f));
                pem[slot][0] = fmaf(h, s_w2[col][0], pem[slot][0]);
                pem[slot][1] = fmaf(h, s_w2[col][1], pem[slot][1]);
                pem[slot][2] = fmaf(h, s_w2[col][2], pem[slot][2]);
            }

    #pragma unroll
    for (int d = 1; d < 4; d <<= 1)
        #pragma unroll
        for (int i = 0; i < 8; ++i)
            #pragma unroll
            for (int k = 0; k < 3; ++k)
                pem[i][k] += __shfl_xor_sync(0xffffffffu, pem[i][k], d);

    if (c == 0) {
        #pragma unroll
        for (int i = 0; i < 8; ++i) {
            const int row = (i >> 1) * 16 + g + (i & 1) * 8;
            atomicAdd(&em_s[row][0], pem[i][0]);
            atomicAdd(&em_s[row][1], pem[i][1]);
            atomicAdd(&em_s[row][2], pem[i][2]);
        }
    }
    __syncthreads();

    if (tid < 192) {
        const int r = tid / 3, k = tid % 3;
        const int m = row_base + r;
        const int b = m >> 9;          // m / 512
        const int t = m & 511;
        g_em[((size_t)t * 3 + k) * BB + b] = em_s[r][k] + b2[k];
    }
}

// ---------------------------------------------------------------------------
// tags transpose: [b][t] -> [t][b]  (+ zero-init the output scalar)
// ---------------------------------------------------------------------------
__global__ void transpose_tags_kernel(const int* __restrict__ tags, float* out) {
    __shared__ int tile[32][33];
    if (blockIdx.x == 0 && blockIdx.y == 0 && threadIdx.x == 0 && threadIdx.y == 0)
        out[0] = 0.0f;
    const int t0 = blockIdx.x * 32;
    const int b0 = blockIdx.y * 32;
    tile[threadIdx.y][threadIdx.x] = tags[(size_t)(b0 + threadIdx.y) * TT + t0 + threadIdx.x];
    __syncthreads();
    g_tagsT[(size_t)(t0 + threadIdx.y) * BB + b0 + threadIdx.x] =
        tile[threadIdx.x][threadIdx.y];
}

// ---------------------------------------------------------------------------
// Kernel 2: CRF. One thread per batch. Statically-unrolled ping-pong
// double buffer (NO runtime buffer index -> everything stays in registers;
// R4's dynamic `cur` index spilled the buffers to local memory).
// ---------------------------------------------------------------------------
__device__ __forceinline__ float sel3(float a, float b, float c, int i) {
    return (i == 0) ? a : ((i == 1) ? b : c);
}
__device__ __forceinline__ float lse3(float x, float y, float z) {
    const float m = fmaxf(fmaxf(x, y), z);
    return m + __logf(__expf(x - m) + __expf(y - m) + __expf(z - m));
}

__device__ __forceinline__ void crf_load8(float (&ec)[8][3], int (&tc)[8],
                                          int base, int b) {
    #pragma unroll
    for (int j = 0; j < 8; ++j) {
        const int t = min(base + j, TT - 1);
        ec[j][0] = g_em[((size_t)t * 3 + 0) * BB + b];
        ec[j][1] = g_em[((size_t)t * 3 + 1) * BB + b];
        ec[j][2] = g_em[((size_t)t * 3 + 2) * BB + b];
        tc[j]    = g_tagsT[(size_t)t * BB + b];
    }
}

struct CrfConst {
    float t00, t01, t02, t10, t11, t12, t20, t21, t22;
};

__device__ __forceinline__ void crf_compute8(const float (&ec)[8][3],
                                             const int (&tc)[8],
                                             int t0, int len,
                                             float& a0, float& a1, float& a2,
                                             float& num, int& tp,
                                             const CrfConst& C) {
    #pragma unroll
    for (int j = 0; j < 8; ++j) {
        const int t = t0 + j;
        if (t >= len) break;
        const float e0 = ec[j][0], e1 = ec[j][1], e2 = ec[j][2];
        const float n0 = lse3(a0 + C.t00, a1 + C.t10, a2 + C.t20) + e0;
        const float n1 = lse3(a0 + C.t01, a1 + C.t11, a2 + C.t21) + e1;
        const float n2 = lse3(a0 + C.t02, a1 + C.t12, a2 + C.t22) + e2;
        a0 = n0; a1 = n1; a2 = n2;

        const int tcur = tc[j];
        const float trv =
            (tp == 0) ? sel3(C.t00, C.t01, C.t02, tcur)
          : (tp == 1) ? sel3(C.t10, C.t11, C.t12, tcur)
                      : sel3(C.t20, C.t21, C.t22, tcur);
        num += trv + sel3(e0, e1, e2, tcur);
        tp = tcur;
    }
}

__global__ void crf_kernel(const int* __restrict__ lengths,
                           const float* __restrict__ trans,
                           const float* __restrict__ start,
                           const float* __restrict__ end,
                           float* __restrict__ out)
{
    const int b = blockIdx.x * 32 + threadIdx.x;   // 0..255

    CrfConst C;
    C.t00 = trans[0]; C.t01 = trans[1]; C.t02 = trans[2];
    C.t10 = trans[3]; C.t11 = trans[4]; C.t12 = trans[5];
    C.t20 = trans[6]; C.t21 = trans[7]; C.t22 = trans[8];
    const float st0 = start[0], st1 = start[1], st2 = start[2];
    const float en0 = end[0],   en1 = end[1],   en2 = end[2];

    const int len = max(lengths[b], 1);

    float e0 = g_em[0 * BB + b];
    float e1 = g_em[1 * BB + b];
    float e2 = g_em[2 * BB + b];
    int tp = g_tagsT[b];
    float num = sel3(st0, st1, st2, tp) + sel3(e0, e1, e2, tp);
    float a0 = st0 + e0, a1 = st1 + e1, a2 = st2 + e2;

    float ecA[8][3], ecB[8][3];
    int   tcA[8],    tcB[8];

    crf_load8(ecA, tcA, 1, b);

    #pragma unroll 1
    for (int t0 = 1; t0 < TT; t0 += 16) {
        if (t0 >= len) break;
        crf_load8(ecB, tcB, t0 + 8, b);                       // overlaps compute A
        crf_compute8(ecA, tcA, t0, len, a0, a1, a2, num, tp, C);
        if (t0 + 8 >= len) break;
        crf_load8(ecA, tcA, t0 + 16, b);                      // overlaps compute B
        crf_compute8(ecB, tcB, t0 + 8, len, a0, a1, a2, num, tp, C);
    }

    num += sel3(en0, en1, en2, tp);
    const float denom = lse3(a0 + en0, a1 + en1, a2 + en2);

    float llh = num - denom;
    #pragma unroll
    for (int off = 16; off > 0; off >>= 1)
        llh += __shfl_xor_sync(0xffffffffu, llh, off);
    if (threadIdx.x == 0)
        atomicAdd(out, -llh * (1.0f / (float)BB));
}

// ---------------------------------------------------------------------------
extern "C" void kernel_launch(void* const* d_in, const int* in_sizes, int n_in,
                              void* d_out, int out_size)
{
    const float* x       = (const float*)d_in[0];
    const int*   tags    = (const int*)  d_in[1];
    const int*   lengths = (const int*)  d_in[2];
    const float* W1      = (const float*)d_in[3];
    const float* b1      = (const float*)d_in[4];
    const float* W2      = (const float*)d_in[5];
    const float* b2      = (const float*)d_in[6];
    const float* trans   = (const float*)d_in[7];
    const float* start   = (const float*)d_in[8];
    const float* end     = (const float*)d_in[9];

    cudaFuncSetAttribute(fused_mlp_tc,
                         cudaFuncAttributeMaxDynamicSharedMemorySize,
                         DYN_SMEM_BYTES);

    fused_mlp_tc<<<MM / 64, 256, DYN_SMEM_BYTES>>>(x, W1, b1, W2, b2);
    transpose_tags_kernel<<<dim3(TT / 32, BB / 32), dim3(32, 32)>>>(tags, (float*)d_out);
    crf_kernel<<<8, 32>>>(lengths, trans, start, end, (float*)d_out);
}

// round 6
// speedup vs baseline: 2.1357x; 1.7152x over previous
#include <cuda_runtime.h>
#include <cuda_bf16.h>
#include <math.h>

// Problem constants
#define BB 256
#define TT 512
#define DD 512
#define HH 256
#define KK 3
#define MM (BB * TT)   // 131072 rows

#define NEG (-1.0e30f)

// Scratch: em row-major [b*T + t][3]
__device__ float g_em[MM * KK];

// ---------------------------------------------------------------------------
// MLP helpers
// ---------------------------------------------------------------------------
__device__ __forceinline__ void mma_tf32(float (&d)[4],
                                         const unsigned (&a)[4],
                                         const unsigned (&b)[2]) {
    asm volatile(
        "mma.sync.aligned.m16n8k8.row.col.f32.tf32.tf32.f32 "
        "{%0,%1,%2,%3}, {%4,%5,%6,%7}, {%8,%9}, {%0,%1,%2,%3};\n"
        : "+f"(d[0]), "+f"(d[1]), "+f"(d[2]), "+f"(d[3])
        : "r"(a[0]), "r"(a[1]), "r"(a[2]), "r"(a[3]),
          "r"(b[0]), "r"(b[1]));
}

#define CP_ASYNC16(dst, src) \
    asm volatile("cp.async.cg.shared.global [%0], [%1], 16;\n" :: "r"(dst), "l"(src))
#define CP_COMMIT() asm volatile("cp.async.commit_group;\n")
#define CP_WAIT(n)  asm volatile("cp.async.wait_group %0;\n" :: "n"(n))

#define SX_STRIDE (64 * 20)
#define SW_STRIDE (16 * 264)
#define DYN_SMEM_BYTES (3 * (SX_STRIDE + SW_STRIDE) * 4)   // 66048

// ---------------------------------------------------------------------------
// Kernel 1: fused  em = gelu(x @ W1 + b1) @ W2 + b2   (tf32 tensor cores)
// Unchanged mainloop (proven 274-290us). Epilogue writes row-major em.
// Block 0 zeroes out[0] for the CRF atomicAdd.
// ---------------------------------------------------------------------------
__global__ __launch_bounds__(256, 2)
void fused_mlp_tc(const float* __restrict__ x,
                  const float* __restrict__ W1,
                  const float* __restrict__ b1,
                  const float* __restrict__ W2,
                  const float* __restrict__ b2,
                  float* __restrict__ out)
{
    extern __shared__ float dsm[];
    float* s_x = dsm;                        // [3][64][20]
    float* s_w = dsm + 3 * SX_STRIDE;        // [3][16][264]

    __shared__ float s_w2[256][3];
    __shared__ float s_b1[256];
    __shared__ float em_s[64][3];

    const int tid  = threadIdx.x;
    const int wid  = tid >> 5;
    const int lane = tid & 31;
    const int g    = lane >> 2;
    const int c    = lane & 3;
    const int row_base = blockIdx.x * 64;
    const int cw   = wid * 32;

    if (blockIdx.x == 0 && tid == 0) out[0] = 0.0f;

    s_b1[tid]    = b1[tid];
    s_w2[tid][0] = W2[tid * 3 + 0];
    s_w2[tid][1] = W2[tid * 3 + 1];
    s_w2[tid][2] = W2[tid * 3 + 2];
    if (tid < 192) ((float*)em_s)[tid] = 0.0f;

    float acc[4][4][4];
    #pragma unroll
    for (int mt = 0; mt < 4; ++mt)
        #pragma unroll
        for (int nt = 0; nt < 4; ++nt)
            #pragma unroll
            for (int e = 0; e < 4; ++e) acc[mt][nt][e] = 0.0f;

    const int xr = tid >> 2;
    const int xq = (tid & 3) << 2;
    auto issue_stage = [&](int s, int k0) {
        unsigned dx = (unsigned)__cvta_generic_to_shared(
            &s_x[s * SX_STRIDE + xr * 20 + xq]);
        CP_ASYNC16(dx, &x[(size_t)(row_base + xr) * DD + k0 + xq]);
        #pragma unroll
        for (int p = 0; p < 4; ++p) {
            const int chunk = tid + p * 256;
            const int kr = chunk >> 6;
            const int c4 = (chunk & 63) << 2;
            unsigned dw = (unsigned)__cvta_generic_to_shared(
                &s_w[s * SW_STRIDE + kr * 264 + c4]);
            CP_ASYNC16(dw, &W1[(size_t)(k0 + kr) * HH + c4]);
        }
        CP_COMMIT();
    };

    issue_stage(0, 0);
    issue_stage(1, 16);

    const int NITER = DD / 16;  // 32
    int cur = 0, wr = 2;

    #pragma unroll 1
    for (int it = 0; it < NITER; ++it) {
        if (it == NITER - 1) { CP_WAIT(0); }
        else                 { CP_WAIT(1); }
        __syncthreads();

        if (it + 2 < NITER) issue_stage(wr, (it + 2) * 16);

        const float* xb = &s_x[cur * SX_STRIDE];
        const float* wb = &s_w[cur * SW_STRIDE];

        #pragma unroll
        for (int ks = 0; ks < 2; ++ks) {
            const int kk = ks * 8;
            unsigned bf[4][2];
            #pragma unroll
            for (int nt = 0; nt < 4; ++nt) {
                const int n = cw + nt * 8 + g;
                bf[nt][0] = __float_as_uint(wb[(kk + c) * 264 + n]);
                bf[nt][1] = __float_as_uint(wb[(kk + c + 4) * 264 + n]);
            }
            #pragma unroll
            for (int mt = 0; mt < 4; ++mt) {
                const int r0 = mt * 16 + g;
                unsigned af[4];
                af[0] = __float_as_uint(xb[r0 * 20 + kk + c]);
                af[1] = __float_as_uint(xb[(r0 + 8) * 20 + kk + c]);
                af[2] = __float_as_uint(xb[r0 * 20 + kk + c + 4]);
                af[3] = __float_as_uint(xb[(r0 + 8) * 20 + kk + c + 4]);
                #pragma unroll
                for (int nt = 0; nt < 4; ++nt)
                    mma_tf32(acc[mt][nt], af, bf[nt]);
            }
        }

        cur = (cur == 2) ? 0 : cur + 1;
        wr  = (wr  == 2) ? 0 : wr  + 1;
    }

    // ---- epilogue ----
    float pem[8][3];
    #pragma unroll
    for (int i = 0; i < 8; ++i)
        #pragma unroll
        for (int k = 0; k < 3; ++k) pem[i][k] = 0.0f;

    #pragma unroll
    for (int mt = 0; mt < 4; ++mt)
        #pragma unroll
        for (int nt = 0; nt < 4; ++nt)
            #pragma unroll
            for (int e = 0; e < 4; ++e) {
                const int col = cw + nt * 8 + 2 * c + (e & 1);
                const int slot = mt * 2 + (e >> 1);
                const float v = acc[mt][nt][e] + s_b1[col];
                const float h = 0.5f * v * (1.0f + erff(v * 0.7071067811865476f));
                pem[slot][0] = fmaf(h, s_w2[col][0], pem[slot][0]);
                pem[slot][1] = fmaf(h, s_w2[col][1], pem[slot][1]);
                pem[slot][2] = fmaf(h, s_w2[col][2], pem[slot][2]);
            }

    #pragma unroll
    for (int d = 1; d < 4; d <<= 1)
        #pragma unroll
        for (int i = 0; i < 8; ++i)
            #pragma unroll
            for (int k = 0; k < 3; ++k)
                pem[i][k] += __shfl_xor_sync(0xffffffffu, pem[i][k], d);

    if (c == 0) {
        #pragma unroll
        for (int i = 0; i < 8; ++i) {
            const int row = (i >> 1) * 16 + g + (i & 1) * 8;
            atomicAdd(&em_s[row][0], pem[i][0]);
            atomicAdd(&em_s[row][1], pem[i][1]);
            atomicAdd(&em_s[row][2], pem[i][2]);
        }
    }
    __syncthreads();

    if (tid < 192) {
        const int k = tid % 3;
        g_em[(size_t)row_base * 3 + tid] = ((float*)em_s)[tid] + b2[k];
    }
}

// ---------------------------------------------------------------------------
// Kernel 2: CRF via log-semiring associative scan. One WARP per batch.
// Lane j composes a 16-step segment of 3x3 step matrices, then an
// order-preserving shuffle butterfly merges the 32 segments.
// ---------------------------------------------------------------------------
__device__ __forceinline__ float sel3(float a, float b, float c, int i) {
    return (i == 0) ? a : ((i == 1) ? b : c);
}
__device__ __forceinline__ float lse3(float x, float y, float z) {
    const float m = fmaxf(fmaxf(x, y), z);
    return m + __logf(__expf(x - m) + __expf(y - m) + __expf(z - m));
}

#define CRF_WARPS 4

__global__ __launch_bounds__(32 * CRF_WARPS)
void crf_kernel(const int* __restrict__ tags,
                const int* __restrict__ lengths,
                const float* __restrict__ trans,
                const float* __restrict__ start,
                const float* __restrict__ end,
                float* __restrict__ out)
{
    __shared__ float s_em[CRF_WARPS][TT * 3];
    __shared__ int   s_tag[CRF_WARPS][TT];
    __shared__ float s_tr[9];

    const int wid  = threadIdx.x >> 5;
    const int lane = threadIdx.x & 31;
    const int b    = blockIdx.x * CRF_WARPS + wid;

    if (threadIdx.x < 9) s_tr[threadIdx.x] = trans[threadIdx.x];
    __syncthreads();

    // stage this batch's em + tags into smem (coalesced vector loads)
    {
        const float4* src = reinterpret_cast<const float4*>(&g_em[(size_t)b * TT * 3]);
        float4* dst = reinterpret_cast<float4*>(s_em[wid]);
        #pragma unroll
        for (int i = 0; i < 12; ++i) dst[lane + i * 32] = src[lane + i * 32];
        const int4* ts = reinterpret_cast<const int4*>(&tags[(size_t)b * TT]);
        int4* td = reinterpret_cast<int4*>(s_tag[wid]);
        #pragma unroll
        for (int i = 0; i < 4; ++i) td[lane + i * 32] = ts[lane + i * 32];
    }
    __syncwarp();

    const float t00 = s_tr[0], t01 = s_tr[1], t02 = s_tr[2];
    const float t10 = s_tr[3], t11 = s_tr[4], t12 = s_tr[5];
    const float t20 = s_tr[6], t21 = s_tr[7], t22 = s_tr[8];
    const float st0 = start[0], st1 = start[1], st2 = start[2];
    const float en0 = end[0],   en1 = end[1],   en2 = end[2];

    const int len = max(lengths[b], 1);
    const float* em = s_em[wid];
    const int*   tg = s_tag[wid];

    // ---- segment matrix: steps t in [1+16*lane, 1+16*lane+16) ∩ [1, len) ----
    const int t0 = 1 + lane * 16;
    float M[3][3];
    if (t0 < len) {
        float e0 = em[t0 * 3 + 0], e1 = em[t0 * 3 + 1], e2 = em[t0 * 3 + 2];
        M[0][0] = t00 + e0; M[0][1] = t01 + e1; M[0][2] = t02 + e2;
        M[1][0] = t10 + e0; M[1][1] = t11 + e1; M[1][2] = t12 + e2;
        M[2][0] = t20 + e0; M[2][1] = t21 + e1; M[2][2] = t22 + e2;
        #pragma unroll 1
        for (int s = 1; s < 16; ++s) {
            const int t = t0 + s;
            if (t >= len) break;
            e0 = em[t * 3 + 0]; e1 = em[t * 3 + 1]; e2 = em[t * 3 + 2];
            float C[3][3];
            #pragma unroll
            for (int i = 0; i < 3; ++i) {
                C[i][0] = lse3(M[i][0] + t00, M[i][1] + t10, M[i][2] + t20) + e0;
                C[i][1] = lse3(M[i][0] + t01, M[i][1] + t11, M[i][2] + t21) + e1;
                C[i][2] = lse3(M[i][0] + t02, M[i][1] + t12, M[i][2] + t22) + e2;
            }
            #pragma unroll
            for (int i = 0; i < 3; ++i)
                #pragma unroll
                for (int k = 0; k < 3; ++k) M[i][k] = C[i][k];
        }
    } else {
        // identity in log space
        #pragma unroll
        for (int i = 0; i < 3; ++i)
            #pragma unroll
            for (int k = 0; k < 3; ++k) M[i][k] = (i == k) ? 0.0f : NEG;
    }

    // ---- numerator partial for this segment ----
    float num = 0.0f;
    {
        int tp = tg[t0 - 1];
        #pragma unroll 1
        for (int s = 0; s < 16; ++s) {
            const int t = t0 + s;
            if (t >= len) break;
            const int tc = tg[t];
            num += s_tr[tp * 3 + tc] + em[t * 3 + tc];
            tp = tc;
        }
    }
    if (lane == 0) {
        const int tag0 = tg[0];
        num += sel3(st0, st1, st2, tag0) + sel3(em[0], em[1], em[2], tag0);
        if (len == 1) num += sel3(en0, en1, en2, tag0);
    }
    {
        const int tl = len - 1;
        if (tl >= t0 && tl < t0 + 16) {
            const int tagl = tg[tl];
            num += sel3(en0, en1, en2, tagl);
        }
    }

    // ---- order-preserving butterfly: Mtot = M(lane0) ∘ M(lane1) ∘ ... ----
    #pragma unroll
    for (int off = 1; off < 32; off <<= 1) {
        float O[3][3];
        #pragma unroll
        for (int i = 0; i < 3; ++i)
            #pragma unroll
            for (int k = 0; k < 3; ++k)
                O[i][k] = __shfl_xor_sync(0xffffffffu, M[i][k], off);
        const bool lower = ((lane & off) == 0);
        float L[3][3], R[3][3];
        #pragma unroll
        for (int i = 0; i < 3; ++i)
            #pragma unroll
            for (int k = 0; k < 3; ++k) {
                L[i][k] = lower ? M[i][k] : O[i][k];
                R[i][k] = lower ? O[i][k] : M[i][k];
            }
        #pragma unroll
        for (int i = 0; i < 3; ++i)
            #pragma unroll
            for (int k = 0; k < 3; ++k)
                M[i][k] = lse3(L[i][0] + R[0][k], L[i][1] + R[1][k], L[i][2] + R[2][k]);
    }

    // warp-sum numerator
    #pragma unroll
    for (int off = 16; off > 0; off >>= 1)
        num += __shfl_xor_sync(0xffffffffu, num, off);

    if (lane == 0) {
        const float a00 = st0 + em[0];
        const float a01 = st1 + em[1];
        const float a02 = st2 + em[2];
        float aT[3];
        #pragma unroll
        for (int k = 0; k < 3; ++k)
            aT[k] = lse3(a00 + M[0][k], a01 + M[1][k], a02 + M[2][k]);
        const float denom = lse3(aT[0] + en0, aT[1] + en1, aT[2] + en2);
        const float llh = num - denom;
        atomicAdd(out, -llh * (1.0f / (float)BB));
    }
}

// ---------------------------------------------------------------------------
extern "C" void kernel_launch(void* const* d_in, const int* in_sizes, int n_in,
                              void* d_out, int out_size)
{
    const float* x       = (const float*)d_in[0];
    const int*   tags    = (const int*)  d_in[1];
    const int*   lengths = (const int*)  d_in[2];
    const float* W1      = (const float*)d_in[3];
    const float* b1      = (const float*)d_in[4];
    const float* W2      = (const float*)d_in[5];
    const float* b2      = (const float*)d_in[6];
    const float* trans   = (const float*)d_in[7];
    const float* start   = (const float*)d_in[8];
    const float* end     = (const float*)d_in[9];

    cudaFuncSetAttribute(fused_mlp_tc,
                         cudaFuncAttributeMaxDynamicSharedMemorySize,
                         DYN_SMEM_BYTES);

    fused_mlp_tc<<<MM / 64, 256, DYN_SMEM_BYTES>>>(x, W1, b1, W2, b2, (float*)d_out);
    crf_kernel<<<BB / CRF_WARPS, 32 * CRF_WARPS>>>(tags, lengths, trans, start, end,
                                                   (float*)d_out);
}

// round 8
// speedup vs baseline: 2.7920x; 1.3073x over previous
#include <cuda_runtime.h>
#include <cuda_bf16.h>
#include <math.h>
#include <stdint.h>

// Problem constants
#define BB 256
#define TT 512
#define DD 512
#define HH 256
#define MM (BB * TT)   // 131072 rows

#define NEG (-1.0e30f)

// Scratch
__device__ float         g_em[MM * 3];        // emissions row-major [m][3]
__device__ __nv_bfloat16 g_W1T[HH * DD];      // W1 transposed -> bf16 [n][k]

// ---------------------------------------------------------------------------
// helpers
// ---------------------------------------------------------------------------
__device__ __forceinline__ unsigned pack_bf16(float lo, float hi) {
    unsigned d;
    asm("cvt.rn.bf16x2.f32 %0, %1, %2;" : "=r"(d) : "f"(hi), "f"(lo));
    return d;
}

__device__ __forceinline__ void mma_bf16(float (&d)[4],
                                         const unsigned (&a)[4],
                                         const unsigned (&b)[2]) {
    asm volatile(
        "mma.sync.aligned.m16n8k16.row.col.f32.bf16.bf16.f32 "
        "{%0,%1,%2,%3}, {%4,%5,%6,%7}, {%8,%9}, {%0,%1,%2,%3};\n"
        : "+f"(d[0]), "+f"(d[1]), "+f"(d[2]), "+f"(d[3])
        : "r"(a[0]), "r"(a[1]), "r"(a[2]), "r"(a[3]),
          "r"(b[0]), "r"(b[1]));
}

#define CP_ASYNC16(dst, src) \
    asm volatile("cp.async.cg.shared.global [%0], [%1], 16;\n" :: "r"(dst), "l"(src))
#define CP_COMMIT() asm volatile("cp.async.commit_group;\n")
#define CP_WAIT(n)  asm volatile("cp.async.wait_group %0;\n" :: "n"(n))

// Stage geometry: K-chunk = 32.
// A: 64 rows x 32 f32, row stride 40 words (conflict-free float2 frag loads)
// B: 256 rows x 32 bf16, row stride 20 words (conflict-free b32 frag loads)
#define A_ROWW 40
#define B_ROWW 20
#define A_ST_BYTES (64 * A_ROWW * 4)    // 10240
#define B_ST_BYTES (256 * B_ROWW * 4)   // 20480
#define STAGE_BYTES (A_ST_BYTES + B_ST_BYTES)   // 30720
#define DYN_SMEM_BYTES (3 * STAGE_BYTES)        // 92160

// ---------------------------------------------------------------------------
// prep: W1 [D][H] f32 -> g_W1T [H][D] bf16 ; zero out[0]
// ---------------------------------------------------------------------------
__global__ void prep_kernel(const float* __restrict__ W1, float* out) {
    __shared__ float tile[32][33];
    const int k0 = blockIdx.x * 32;
    const int n0 = blockIdx.y * 32;
    if (blockIdx.x == 0 && blockIdx.y == 0 && threadIdx.x == 0 && threadIdx.y == 0)
        out[0] = 0.0f;
    tile[threadIdx.y][threadIdx.x] = W1[(size_t)(k0 + threadIdx.y) * HH + n0 + threadIdx.x];
    __syncthreads();
    g_W1T[(size_t)(n0 + threadIdx.y) * DD + k0 + threadIdx.x] =
        __float2bfloat16(tile[threadIdx.x][threadIdx.y]);
}

// ---------------------------------------------------------------------------
// Kernel 1: fused  em = gelu(x @ W1 + b1) @ W2 + b2   via bf16 m16n8k16.
// Block 256 thr (8 warps), BM=64, BN=256 (full H), BK=32, 3-stage cp.async.
// Warp w owns cols [w*32, w*32+32): 4mt x 4nt tiles of m16n8k16.
// x stays f32 in smem, converted to bf16 in registers at frag-load time.
// W1T tiles arrive pre-converted bf16.
// ---------------------------------------------------------------------------
__global__ __launch_bounds__(256, 2)
void fused_mlp_bf16(const float* __restrict__ x,
                    const float* __restrict__ b1,
                    const float* __restrict__ W2,
                    const float* __restrict__ b2)
{
    extern __shared__ float dsm[];

    __shared__ float s_w2[256][3];
    __shared__ float s_b1[256];
    __shared__ float em_s[64][3];

    const int tid  = threadIdx.x;
    const int wid  = tid >> 5;
    const int lane = tid & 31;
    const int g    = lane >> 2;   // row-in-8
    const int c    = lane & 3;    // pair selector
    const int row_base = blockIdx.x * 64;
    const int cw   = wid * 32;

    s_b1[tid]    = b1[tid];
    s_w2[tid][0] = W2[tid * 3 + 0];
    s_w2[tid][1] = W2[tid * 3 + 1];
    s_w2[tid][2] = W2[tid * 3 + 2];
    if (tid < 192) ((float*)em_s)[tid] = 0.0f;

    float acc[4][4][4];
    #pragma unroll
    for (int mt = 0; mt < 4; ++mt)
        #pragma unroll
        for (int nt = 0; nt < 4; ++nt)
            #pragma unroll
            for (int e = 0; e < 4; ++e) acc[mt][nt][e] = 0.0f;

    // ---- async stage loader (k-chunk of 32) ----
    auto issue_stage = [&](int s, int k0) {
        const uint32_t base = (uint32_t)__cvta_generic_to_shared(dsm) + s * STAGE_BYTES;
        // A: x[row_base+r][k0 + ch*4 ..+4), 512 chunks of 16B
        #pragma unroll
        for (int i = 0; i < 2; ++i) {
            const int id = tid + i * 256;
            const int r = id >> 3, ch = id & 7;
            CP_ASYNC16(base + r * (A_ROWW * 4) + ch * 16,
                       &x[(size_t)(row_base + r) * DD + k0 + ch * 4]);
        }
        // B: W1T[n][k0 + j*8 ..+8) bf16, 1024 chunks of 16B
        #pragma unroll
        for (int i = 0; i < 4; ++i) {
            const int id = tid + i * 256;
            const int n = id >> 2, j = id & 3;
            CP_ASYNC16(base + A_ST_BYTES + n * (B_ROWW * 4) + j * 16,
                       &g_W1T[(size_t)n * DD + k0 + j * 8]);
        }
        CP_COMMIT();
    };

    issue_stage(0, 0);
    issue_stage(1, 32);

    const int NST = DD / 32;   // 16
    int cur = 0, wr = 2;

    #pragma unroll 1
    for (int it = 0; it < NST; ++it) {
        if (it == NST - 1) { CP_WAIT(0); } else { CP_WAIT(1); }
        __syncthreads();

        if (it + 2 < NST) issue_stage(wr, (it + 2) * 32);

        const float*    xa = dsm + cur * (STAGE_BYTES / 4);
        const uint32_t* bw = (const uint32_t*)(xa + A_ST_BYTES / 4);

        #pragma unroll
        for (int ks = 0; ks < 2; ++ks) {
            const int kk = ks * 16;   // bf16-k base within chunk
            // B frags: word = n*20 + kk/2 + c  (b0), +4 (b1)
            unsigned bf[4][2];
            #pragma unroll
            for (int nt = 0; nt < 4; ++nt) {
                const int n = cw + nt * 8 + g;
                const int w0 = n * B_ROWW + (kk >> 1) + c;
                bf[nt][0] = bw[w0];
                bf[nt][1] = bw[w0 + 4];
            }
            #pragma unroll
            for (int mt = 0; mt < 4; ++mt) {
                const int r0 = mt * 16 + g;
                const float2 p00 = *(const float2*)&xa[r0 * A_ROWW + kk + 2 * c];
                const float2 p01 = *(const float2*)&xa[r0 * A_ROWW + kk + 2 * c + 8];
                const float2 p10 = *(const float2*)&xa[(r0 + 8) * A_ROWW + kk + 2 * c];
                const float2 p11 = *(const float2*)&xa[(r0 + 8) * A_ROWW + kk + 2 * c + 8];
                unsigned af[4];
                af[0] = pack_bf16(p00.x, p00.y);
                af[1] = pack_bf16(p10.x, p10.y);
                af[2] = pack_bf16(p01.x, p01.y);
                af[3] = pack_bf16(p11.x, p11.y);
                #pragma unroll
                for (int nt = 0; nt < 4; ++nt)
                    mma_bf16(acc[mt][nt], af, bf[nt]);
            }
        }

        cur = (cur == 2) ? 0 : cur + 1;
        wr  = (wr  == 2) ? 0 : wr  + 1;
    }

    // ---- epilogue: bias + exact gelu + W2 contraction ----
    float pem[8][3];
    #pragma unroll
    for (int i = 0; i < 8; ++i)
        #pragma unroll
        for (int k = 0; k < 3; ++k) pem[i][k] = 0.0f;

    #pragma unroll
    for (int mt = 0; mt < 4; ++mt)
        #pragma unroll
        for (int nt = 0; nt < 4; ++nt)
            #pragma unroll
            for (int e = 0; e < 4; ++e) {
                const int col = cw + nt * 8 + 2 * c + (e & 1);
                const int slot = mt * 2 + (e >> 1);
                const float v = acc[mt][nt][e] + s_b1[col];
                const float h = 0.5f * v * (1.0f + erff(v * 0.7071067811865476f));
                pem[slot][0] = fmaf(h, s_w2[col][0], pem[slot][0]);
                pem[slot][1] = fmaf(h, s_w2[col][1], pem[slot][1]);
                pem[slot][2] = fmaf(h, s_w2[col][2], pem[slot][2]);
            }

    #pragma unroll
    for (int d = 1; d < 4; d <<= 1)
        #pragma unroll
        for (int i = 0; i < 8; ++i)
            #pragma unroll
            for (int k = 0; k < 3; ++k)
                pem[i][k] += __shfl_xor_sync(0xffffffffu, pem[i][k], d);

    if (c == 0) {
        #pragma unroll
        for (int i = 0; i < 8; ++i) {
            const int row = (i >> 1) * 16 + g + (i & 1) * 8;
            atomicAdd(&em_s[row][0], pem[i][0]);
            atomicAdd(&em_s[row][1], pem[i][1]);
            atomicAdd(&em_s[row][2], pem[i][2]);
        }
    }
    __syncthreads();

    if (tid < 192) {
        g_em[(size_t)row_base * 3 + tid] = ((float*)em_s)[tid] + b2[tid % 3];
    }
}

// ---------------------------------------------------------------------------
// Kernel 2: CRF via log-semiring associative scan (unchanged, proven 12us).
// ---------------------------------------------------------------------------
__device__ __forceinline__ float sel3(float a, float b, float c, int i) {
    return (i == 0) ? a : ((i == 1) ? b : c);
}
__device__ __forceinline__ float lse3(float x, float y, float z) {
    const float m = fmaxf(fmaxf(x, y), z);
    return m + __logf(__expf(x - m) + __expf(y - m) + __expf(z - m));
}

#define CRF_WARPS 4

__global__ __launch_bounds__(32 * CRF_WARPS)
void crf_kernel(const int* __restrict__ tags,
                const int* __restrict__ lengths,
                const float* __restrict__ trans,
                const float* __restrict__ start,
                const float* __restrict__ end,
                float* __restrict__ out)
{
    __shared__ float s_em[CRF_WARPS][TT * 3];
    __shared__ int   s_tag[CRF_WARPS][TT];
    __shared__ float s_tr[9];

    const int wid  = threadIdx.x >> 5;
    const int lane = threadIdx.x & 31;
    const int b    = blockIdx.x * CRF_WARPS + wid;

    if (threadIdx.x < 9) s_tr[threadIdx.x] = trans[threadIdx.x];
    __syncthreads();

    {
        const float4* src = reinterpret_cast<const float4*>(&g_em[(size_t)b * TT * 3]);
        float4* dst = reinterpret_cast<float4*>(s_em[wid]);
        #pragma unroll
        for (int i = 0; i < 12; ++i) dst[lane + i * 32] = src[lane + i * 32];
        const int4* ts = reinterpret_cast<const int4*>(&tags[(size_t)b * TT]);
        int4* td = reinterpret_cast<int4*>(s_tag[wid]);
        #pragma unroll
        for (int i = 0; i < 4; ++i) td[lane + i * 32] = ts[lane + i * 32];
    }
    __syncwarp();

    const float t00 = s_tr[0], t01 = s_tr[1], t02 = s_tr[2];
    const float t10 = s_tr[3], t11 = s_tr[4], t12 = s_tr[5];
    const float t20 = s_tr[6], t21 = s_tr[7], t22 = s_tr[8];
    const float st0 = start[0], st1 = start[1], st2 = start[2];
    const float en0 = end[0],   en1 = end[1],   en2 = end[2];

    const int len = max(lengths[b], 1);
    const float* em = s_em[wid];
    const int*   tg = s_tag[wid];

    const int t0 = 1 + lane * 16;
    float M[3][3];
    if (t0 < len) {
        float e0 = em[t0 * 3 + 0], e1 = em[t0 * 3 + 1], e2 = em[t0 * 3 + 2];
        M[0][0] = t00 + e0; M[0][1] = t01 + e1; M[0][2] = t02 + e2;
        M[1][0] = t10 + e0; M[1][1] = t11 + e1; M[1][2] = t12 + e2;
        M[2][0] = t20 + e0; M[2][1] = t21 + e1; M[2][2] = t22 + e2;
        #pragma unroll 1
        for (int s = 1; s < 16; ++s) {
            const int t = t0 + s;
            if (t >= len) break;
            e0 = em[t * 3 + 0]; e1 = em[t * 3 + 1]; e2 = em[t * 3 + 2];
            float C[3][3];
            #pragma unroll
            for (int i = 0; i < 3; ++i) {
                C[i][0] = lse3(M[i][0] + t00, M[i][1] + t10, M[i][2] + t20) + e0;
                C[i][1] = lse3(M[i][0] + t01, M[i][1] + t11, M[i][2] + t21) + e1;
                C[i][2] = lse3(M[i][0] + t02, M[i][1] + t12, M[i][2] + t22) + e2;
            }
            #pragma unroll
            for (int i = 0; i < 3; ++i)
                #pragma unroll
                for (int k = 0; k < 3; ++k) M[i][k] = C[i][k];
        }
    } else {
        #pragma unroll
        for (int i = 0; i < 3; ++i)
            #pragma unroll
            for (int k = 0; k < 3; ++k) M[i][k] = (i == k) ? 0.0f : NEG;
    }

    float num = 0.0f;
    {
        int tp = tg[t0 - 1];
        #pragma unroll 1
        for (int s = 0; s < 16; ++s) {
            const int t = t0 + s;
            if (t >= len) break;
            const int tc = tg[t];
            num += s_tr[tp * 3 + tc] + em[t * 3 + tc];
            tp = tc;
        }
    }
    if (lane == 0) {
        const int tag0 = tg[0];
        num += sel3(st0, st1, st2, tag0) + sel3(em[0], em[1], em[2], tag0);
        if (len == 1) num += sel3(en0, en1, en2, tag0);
    }
    {
        const int tl = len - 1;
        if (tl >= t0 && tl < t0 + 16) num += sel3(en0, en1, en2, tg[tl]);
    }

    #pragma unroll
    for (int off = 1; off < 32; off <<= 1) {
        float O[3][3];
        #pragma unroll
        for (int i = 0; i < 3; ++i)
            #pragma unroll
            for (int k = 0; k < 3; ++k)
                O[i][k] = __shfl_xor_sync(0xffffffffu, M[i][k], off);
        const bool lower = ((lane & off) == 0);
        float L[3][3], R[3][3];
        #pragma unroll
        for (int i = 0; i < 3; ++i)
            #pragma unroll
            for (int k = 0; k < 3; ++k) {
                L[i][k] = lower ? M[i][k] : O[i][k];
                R[i][k] = lower ? O[i][k] : M[i][k];
            }
        #pragma unroll
        for (int i = 0; i < 3; ++i)
            #pragma unroll
            for (int k = 0; k < 3; ++k)
                M[i][k] = lse3(L[i][0] + R[0][k], L[i][1] + R[1][k], L[i][2] + R[2][k]);
    }

    #pragma unroll
    for (int off = 16; off > 0; off >>= 1)
        num += __shfl_xor_sync(0xffffffffu, num, off);

    if (lane == 0) {
        const float a00 = st0 + em[0];
        const float a01 = st1 + em[1];
        const float a02 = st2 + em[2];
        float aT[3];
        #pragma unroll
        for (int k = 0; k < 3; ++k)
            aT[k] = lse3(a00 + M[0][k], a01 + M[1][k], a02 + M[2][k]);
        const float denom = lse3(aT[0] + en0, aT[1] + en1, aT[2] + en2);
        atomicAdd(out, -(num - denom) * (1.0f / (float)BB));
    }
}

// ---------------------------------------------------------------------------
extern "C" void kernel_launch(void* const* d_in, const int* in_sizes, int n_in,
                              void* d_out, int out_size)
{
    const float* x       = (const float*)d_in[0];
    const int*   tags    = (const int*)  d_in[1];
    const int*   lengths = (const int*)  d_in[2];
    const float* W1      = (const float*)d_in[3];
    const float* b1      = (const float*)d_in[4];
    const float* W2      = (const float*)d_in[5];
    const float* b2      = (const float*)d_in[6];
    const float* trans   = (const float*)d_in[7];
    const float* start   = (const float*)d_in[8];
    const float* end     = (const float*)d_in[9];

    cudaFuncSetAttribute(fused_mlp_bf16,
                         cudaFuncAttributeMaxDynamicSharedMemorySize,
                         DYN_SMEM_BYTES);

    prep_kernel<<<dim3(DD / 32, HH / 32), dim3(32, 32)>>>(W1, (float*)d_out);
    fused_mlp_bf16<<<MM / 64, 256, DYN_SMEM_BYTES>>>(x, b1, W2, b2);
    crf_kernel<<<BB / CRF_WARPS, 32 * CRF_WARPS>>>(tags, lengths, trans, start, end,
                                                   (float*)d_out);
}

// round 9
// speedup vs baseline: 2.9632x; 1.0613x over previous
#include <cuda_runtime.h>
#include <cuda_bf16.h>
#include <math.h>
#include <stdint.h>

// Problem constants
#define BB 256
#define TT 512
#define DD 512
#define HH 256
#define MM (BB * TT)   // 131072 rows

#define NEG (-1.0e30f)

// Scratch
__device__ float         g_em[MM * 3];        // emissions row-major [m][3]
__device__ __nv_bfloat16 g_W1T[HH * DD];      // W1 transposed -> bf16 [n][k]

// ---------------------------------------------------------------------------
// helpers
// ---------------------------------------------------------------------------
__device__ __forceinline__ unsigned pack_bf16(float lo, float hi) {
    unsigned d;
    asm("cvt.rn.bf16x2.f32 %0, %1, %2;" : "=r"(d) : "f"(hi), "f"(lo));
    return d;
}

__device__ __forceinline__ void mma_bf16(float (&d)[4],
                                         const unsigned (&a)[4],
                                         const unsigned (&b)[2]) {
    asm volatile(
        "mma.sync.aligned.m16n8k16.row.col.f32.bf16.bf16.f32 "
        "{%0,%1,%2,%3}, {%4,%5,%6,%7}, {%8,%9}, {%0,%1,%2,%3};\n"
        : "+f"(d[0]), "+f"(d[1]), "+f"(d[2]), "+f"(d[3])
        : "r"(a[0]), "r"(a[1]), "r"(a[2]), "r"(a[3]),
          "r"(b[0]), "r"(b[1]));
}

#define CP_ASYNC16(dst, src) \
    asm volatile("cp.async.cg.shared.global [%0], [%1], 16;\n" :: "r"(dst), "l"(src))
#define CP_COMMIT() asm volatile("cp.async.commit_group;\n")
#define CP_WAIT(n)  asm volatile("cp.async.wait_group %0;\n" :: "n"(n))

// Geometry: K-chunk 32.
// B (bf16, cp.async, 3 stages): 256 rows x 16 words + 4 pad = 20 words/row.
// A (bf16, LDG->cvt->STS, 2 buffers): 64 rows x 16 words + 4 pad = 20 words/row.
#define B_ROWW 20
#define B_ST_WORDS (256 * B_ROWW)            // 5120 words / stage
#define B_TOTAL_WORDS (3 * B_ST_WORDS)       // 15360
#define A_ROWW 20
#define A_BUF_WORDS (64 * A_ROWW)            // 1280 words / buffer
#define DYN_SMEM_BYTES ((B_TOTAL_WORDS + 2 * A_BUF_WORDS) * 4)   // 71680

// ---------------------------------------------------------------------------
// prep: W1 [D][H] f32 -> g_W1T [H][D] bf16 ; zero out[0]
// ---------------------------------------------------------------------------
__global__ void prep_kernel(const float* __restrict__ W1, float* out) {
    __shared__ float tile[32][33];
    const int k0 = blockIdx.x * 32;
    const int n0 = blockIdx.y * 32;
    if (blockIdx.x == 0 && blockIdx.y == 0 && threadIdx.x == 0 && threadIdx.y == 0)
        out[0] = 0.0f;
    tile[threadIdx.y][threadIdx.x] = W1[(size_t)(k0 + threadIdx.y) * HH + n0 + threadIdx.x];
    __syncthreads();
    g_W1T[(size_t)(n0 + threadIdx.y) * DD + k0 + threadIdx.x] =
        __float2bfloat16(tile[threadIdx.x][threadIdx.y]);
}

// ---------------------------------------------------------------------------
// Kernel 1: fused  em = gelu(x @ W1 + b1) @ W2 + b2   via bf16 m16n8k16.
// Block 256 thr (8 warps), BM=64, BN=256, BK=32.
// A path: LDG f32 (chunk it+2) -> regs -> cvt -> STS bf16 tile (chunk it+1),
//         frag loads are plain LDS.32 (no per-frag cvt, half the bytes).
// B path: pre-converted bf16 W1T via 3-stage cp.async (proven).
// One __syncthreads per chunk.
// ---------------------------------------------------------------------------
__global__ __launch_bounds__(256, 2)
void fused_mlp_bf16(const float* __restrict__ x,
                    const float* __restrict__ b1,
                    const float* __restrict__ W2,
                    const float* __restrict__ b2)
{
    extern __shared__ uint32_t dsm[];
    uint32_t* bsm = dsm;                      // B stages: 3 x 5120 words
    uint32_t* asm0 = dsm + B_TOTAL_WORDS;     // A buffer 0: 1280 words
    uint32_t* asm1 = asm0 + A_BUF_WORDS;      // A buffer 1

    __shared__ float s_w2[256][3];
    __shared__ float s_b1[256];
    __shared__ float em_s[64][3];

    const int tid  = threadIdx.x;
    const int wid  = tid >> 5;
    const int lane = tid & 31;
    const int g    = lane >> 2;
    const int c    = lane & 3;
    const int row_base = blockIdx.x * 64;
    const int cw   = wid * 32;

    s_b1[tid]    = b1[tid];
    s_w2[tid][0] = W2[tid * 3 + 0];
    s_w2[tid][1] = W2[tid * 3 + 1];
    s_w2[tid][2] = W2[tid * 3 + 2];
    if (tid < 192) ((float*)em_s)[tid] = 0.0f;

    float acc[4][4][4];
    #pragma unroll
    for (int mt = 0; mt < 4; ++mt)
        #pragma unroll
        for (int nt = 0; nt < 4; ++nt)
            #pragma unroll
            for (int e = 0; e < 4; ++e) acc[mt][nt][e] = 0.0f;

    // ---- A chunk loader: thread covers x[ar0/ar1][k0 + 4*ach0/1 ..+4) ----
    const int ar0 = tid >> 3,           ach0 = tid & 7;
    const int ar1 = (tid + 256) >> 3,   ach1 = (tid + 256) & 7;
    auto ldgA = [&](float4& v0, float4& v1, int k0) {
        v0 = *(const float4*)&x[(size_t)(row_base + ar0) * DD + k0 + ach0 * 4];
        v1 = *(const float4*)&x[(size_t)(row_base + ar1) * DD + k0 + ach1 * 4];
    };
    auto stsA = [&](uint32_t* abuf, const float4& v0, const float4& v1) {
        uint2 w0 = make_uint2(pack_bf16(v0.x, v0.y), pack_bf16(v0.z, v0.w));
        uint2 w1 = make_uint2(pack_bf16(v1.x, v1.y), pack_bf16(v1.z, v1.w));
        *(uint2*)&abuf[ar0 * A_ROWW + ach0 * 2] = w0;
        *(uint2*)&abuf[ar1 * A_ROWW + ach1 * 2] = w1;
    };

    // ---- B stage loader ----
    auto issueB = [&](int s, int k0) {
        const uint32_t base = (uint32_t)__cvta_generic_to_shared(bsm) + s * (B_ST_WORDS * 4);
        #pragma unroll
        for (int i = 0; i < 4; ++i) {
            const int id = tid + i * 256;
            const int n = id >> 2, j = id & 3;
            CP_ASYNC16(base + n * (B_ROWW * 4) + j * 16,
                       &g_W1T[(size_t)n * DD + k0 + j * 8]);
        }
        CP_COMMIT();
    };

    // ---- compute one chunk from {A buffer, B stage} ----
    auto compute = [&](const uint32_t* aw, const uint32_t* bw) {
        #pragma unroll
        for (int ks = 0; ks < 2; ++ks) {
            const int kw = ks * 8;   // word base within row
            unsigned bf[4][2];
            #pragma unroll
            for (int nt = 0; nt < 4; ++nt) {
                const int n = cw + nt * 8 + g;
                bf[nt][0] = bw[n * B_ROWW + kw + c];
                bf[nt][1] = bw[n * B_ROWW + kw + c + 4];
            }
            #pragma unroll
            for (int mt = 0; mt < 4; ++mt) {
                const int r0 = mt * 16 + g;
                unsigned af[4];
                af[0] = aw[r0 * A_ROWW + kw + c];
                af[1] = aw[(r0 + 8) * A_ROWW + kw + c];
                af[2] = aw[r0 * A_ROWW + kw + c + 4];
                af[3] = aw[(r0 + 8) * A_ROWW + kw + c + 4];
                #pragma unroll
                for (int nt = 0; nt < 4; ++nt)
                    mma_bf16(acc[mt][nt], af, bf[nt]);
            }
        }
    };

    // ---- prologue ----
    float4 raA0, raA1;   // A f32 regs, pipeline slot A
    float4 raB0, raB1;   // pipeline slot B
    ldgA(raA0, raA1, 0);
    stsA(asm0, raA0, raA1);          // chunk 0 -> buf0
    issueB(0, 0);
    issueB(1, 32);
    ldgA(raA0, raA1, 32);            // chunk 1 f32 in slot A

    const int NST = DD / 32;   // 16 chunks, unrolled x2 (static reg ping-pong)
    #pragma unroll 1
    for (int it = 0; it < NST; it += 2) {
        // ---- even chunk `it`: A buf = it&1 = 0 ----
        if (it == NST - 2) { CP_WAIT(1); } else { CP_WAIT(1); }
        __syncthreads();
        // STS chunk it+1 (regs slot A) -> buf1 ; LDG chunk it+2 -> slot B
        stsA(asm1, raA0, raA1);
        if (it + 2 < NST) { ldgA(raB0, raB1, (it + 2) * 32); issueB((it + 2) % 3, (it + 2) * 32); }
        compute(asm0, bsm + (it % 3) * B_ST_WORDS);

        // ---- odd chunk `it+1`: A buf = 1 ----
        if (it + 1 == NST - 1) { CP_WAIT(0); } else { CP_WAIT(1); }
        __syncthreads();
        stsA(asm0, raB0, raB1);      // chunk it+2 -> buf0 (harmless garbage if past end)
        if (it + 3 < NST) { ldgA(raA0, raA1, (it + 3) * 32); issueB((it + 3) % 3, (it + 3) * 32); }
        compute(asm1, bsm + ((it + 1) % 3) * B_ST_WORDS);
    }

    // ---- epilogue: bias + exact gelu + W2 contraction ----
    float pem[8][3];
    #pragma unroll
    for (int i = 0; i < 8; ++i)
        #pragma unroll
        for (int k = 0; k < 3; ++k) pem[i][k] = 0.0f;

    #pragma unroll
    for (int mt = 0; mt < 4; ++mt)
        #pragma unroll
        for (int nt = 0; nt < 4; ++nt)
            #pragma unroll
            for (int e = 0; e < 4; ++e) {
                const int col = cw + nt * 8 + 2 * c + (e & 1);
                const int slot = mt * 2 + (e >> 1);
                const float v = acc[mt][nt][e] + s_b1[col];
                const float h = 0.5f * v * (1.0f + erff(v * 0.7071067811865476f));
                pem[slot][0] = fmaf(h, s_w2[col][0], pem[slot][0]);
                pem[slot][1] = fmaf(h, s_w2[col][1], pem[slot][1]);
                pem[slot][2] = fmaf(h, s_w2[col][2], pem[slot][2]);
            }

    #pragma unroll
    for (int d = 1; d < 4; d <<= 1)
        #pragma unroll
        for (int i = 0; i < 8; ++i)
            #pragma unroll
            for (int k = 0; k < 3; ++k)
                pem[i][k] += __shfl_xor_sync(0xffffffffu, pem[i][k], d);

    if (c == 0) {
        #pragma unroll
        for (int i = 0; i < 8; ++i) {
            const int row = (i >> 1) * 16 + g + (i & 1) * 8;
            atomicAdd(&em_s[row][0], pem[i][0]);
            atomicAdd(&em_s[row][1], pem[i][1]);
            atomicAdd(&em_s[row][2], pem[i][2]);
        }
    }
    __syncthreads();

    if (tid < 192) {
        g_em[(size_t)row_base * 3 + tid] = ((float*)em_s)[tid] + b2[tid % 3];
    }
}

// ---------------------------------------------------------------------------
// Kernel 2: CRF via log-semiring associative scan (unchanged, proven 12us).
// ---------------------------------------------------------------------------
__device__ __forceinline__ float sel3(float a, float b, float c, int i) {
    return (i == 0) ? a : ((i == 1) ? b : c);
}
__device__ __forceinline__ float lse3(float x, float y, float z) {
    const float m = fmaxf(fmaxf(x, y), z);
    return m + __logf(__expf(x - m) + __expf(y - m) + __expf(z - m));
}

#define CRF_WARPS 4

__global__ __launch_bounds__(32 * CRF_WARPS)
void crf_kernel(const int* __restrict__ tags,
                const int* __restrict__ lengths,
                const float* __restrict__ trans,
                const float* __restrict__ start,
                const float* __restrict__ end,
                float* __restrict__ out)
{
    __shared__ float s_em[CRF_WARPS][TT * 3];
    __shared__ int   s_tag[CRF_WARPS][TT];
    __shared__ float s_tr[9];

    const int wid  = threadIdx.x >> 5;
    const int lane = threadIdx.x & 31;
    const int b    = blockIdx.x * CRF_WARPS + wid;

    if (threadIdx.x < 9) s_tr[threadIdx.x] = trans[threadIdx.x];
    __syncthreads();

    {
        const float4* src = reinterpret_cast<const float4*>(&g_em[(size_t)b * TT * 3]);
        float4* dst = reinterpret_cast<float4*>(s_em[wid]);
        #pragma unroll
        for (int i = 0; i < 12; ++i) dst[lane + i * 32] = src[lane + i * 32];
        const int4* ts = reinterpret_cast<const int4*>(&tags[(size_t)b * TT]);
        int4* td = reinterpret_cast<int4*>(s_tag[wid]);
        #pragma unroll
        for (int i = 0; i < 4; ++i) td[lane + i * 32] = ts[lane + i * 32];
    }
    __syncwarp();

    const float t00 = s_tr[0], t01 = s_tr[1], t02 = s_tr[2];
    const float t10 = s_tr[3], t11 = s_tr[4], t12 = s_tr[5];
    const float t20 = s_tr[6], t21 = s_tr[7], t22 = s_tr[8];
    const float st0 = start[0], st1 = start[1], st2 = start[2];
    const float en0 = end[0],   en1 = end[1],   en2 = end[2];

    const int len = max(lengths[b], 1);
    const float* em = s_em[wid];
    const int*   tg = s_tag[wid];

    const int t0 = 1 + lane * 16;
    float M[3][3];
    if (t0 < len) {
        float e0 = em[t0 * 3 + 0], e1 = em[t0 * 3 + 1], e2 = em[t0 * 3 + 2];
        M[0][0] = t00 + e0; M[0][1] = t01 + e1; M[0][2] = t02 + e2;
        M[1][0] = t10 + e0; M[1][1] = t11 + e1; M[1][2] = t12 + e2;
        M[2][0] = t20 + e0; M[2][1] = t21 + e1; M[2][2] = t22 + e2;
        #pragma unroll 1
        for (int s = 1; s < 16; ++s) {
            const int t = t0 + s;
            if (t >= len) break;
            e0 = em[t * 3 + 0]; e1 = em[t * 3 + 1]; e2 = em[t * 3 + 2];
            float C[3][3];
            #pragma unroll
            for (int i = 0; i < 3; ++i) {
                C[i][0] = lse3(M[i][0] + t00, M[i][1] + t10, M[i][2] + t20) + e0;
                C[i][1] = lse3(M[i][0] + t01, M[i][1] + t11, M[i][2] + t21) + e1;
                C[i][2] = lse3(M[i][0] + t02, M[i][1] + t12, M[i][2] + t22) + e2;
            }
            #pragma unroll
            for (int i = 0; i < 3; ++i)
                #pragma unroll
                for (int k = 0; k < 3; ++k) M[i][k] = C[i][k];
        }
    } else {
        #pragma unroll
        for (int i = 0; i < 3; ++i)
            #pragma unroll
            for (int k = 0; k < 3; ++k) M[i][k] = (i == k) ? 0.0f : NEG;
    }

    float num = 0.0f;
    {
        int tp = tg[t0 - 1];
        #pragma unroll 1
        for (int s = 0; s < 16; ++s) {
            const int t = t0 + s;
            if (t >= len) break;
            const int tc = tg[t];
            num += s_tr[tp * 3 + tc] + em[t * 3 + tc];
            tp = tc;
        }
    }
    if (lane == 0) {
        const int tag0 = tg[0];
        num += sel3(st0, st1, st2, tag0) + sel3(em[0], em[1], em[2], tag0);
        if (len == 1) num += sel3(en0, en1, en2, tag0);
    }
    {
        const int tl = len - 1;
        if (tl >= t0 && tl < t0 + 16) num += sel3(en0, en1, en2, tg[tl]);
    }

    #pragma unroll
    for (int off = 1; off < 32; off <<= 1) {
        float O[3][3];
        #pragma unroll
        for (int i = 0; i < 3; ++i)
            #pragma unroll
            for (int k = 0; k < 3; ++k)
                O[i][k] = __shfl_xor_sync(0xffffffffu, M[i][k], off);
        const bool lower = ((lane & off) == 0);
        float L[3][3], R[3][3];
        #pragma unroll
        for (int i = 0; i < 3; ++i)
            #pragma unroll
            for (int k = 0; k < 3; ++k) {
                L[i][k] = lower ? M[i][k] : O[i][k];
                R[i][k] = lower ? O[i][k] : M[i][k];
            }
        #pragma unroll
        for (int i = 0; i < 3; ++i)
            #pragma unroll
            for (int k = 0; k < 3; ++k)
                M[i][k] = lse3(L[i][0] + R[0][k], L[i][1] + R[1][k], L[i][2] + R[2][k]);
    }

    #pragma unroll
    for (int off = 16; off > 0; off >>= 1)
        num += __shfl_xor_sync(0xffffffffu, num, off);

    if (lane == 0) {
        const float a00 = st0 + em[0];
        const float a01 = st1 + em[1];
        const float a02 = st2 + em[2];
        float aT[3];
        #pragma unroll
        for (int k = 0; k < 3; ++k)
            aT[k] = lse3(a00 + M[0][k], a01 + M[1][k], a02 + M[2][k]);
        const float denom = lse3(aT[0] + en0, aT[1] + en1, aT[2] + en2);
        atomicAdd(out, -(num - denom) * (1.0f / (float)BB));
    }
}

// ---------------------------------------------------------------------------
extern "C" void kernel_launch(void* const* d_in, const int* in_sizes, int n_in,
                              void* d_out, int out_size)
{
    const float* x       = (const float*)d_in[0];
    const int*   tags    = (const int*)  d_in[1];
    const int*   lengths = (const int*)  d_in[2];
    const float* W1      = (const float*)d_in[3];
    const float* b1      = (const float*)d_in[4];
    const float* W2      = (const float*)d_in[5];
    const float* b2      = (const float*)d_in[6];
    const float* trans   = (const float*)d_in[7];
    const float* start   = (const float*)d_in[8];
    const float* end     = (const float*)d_in[9];

    cudaFuncSetAttribute(fused_mlp_bf16,
                         cudaFuncAttributeMaxDynamicSharedMemorySize,
                         DYN_SMEM_BYTES);

    prep_kernel<<<dim3(DD / 32, HH / 32), dim3(32, 32)>>>(W1, (float*)d_out);
    fused_mlp_bf16<<<MM / 64, 256, DYN_SMEM_BYTES>>>(x, b1, W2, b2);
    crf_kernel<<<BB / CRF_WARPS, 32 * CRF_WARPS>>>(tags, lengths, trans, start, end,
                                                   (float*)d_out);
}

// round 10
// speedup vs baseline: 3.0692x; 1.0357x over previous
#include <cuda_runtime.h>
#include <cuda_bf16.h>
#include <math.h>
#include <stdint.h>

// Problem constants
#define BB 256
#define TT 512
#define DD 512
#define HH 256
#define MM (BB * TT)   // 131072 rows

#define NEG (-1.0e30f)

// Scratch
__device__ float         g_em[MM * 3];        // emissions row-major [m][3]
__device__ __nv_bfloat16 g_W1T[HH * DD];      // W1 transposed -> bf16 [n][k]

// ---------------------------------------------------------------------------
// helpers
// ---------------------------------------------------------------------------
__device__ __forceinline__ unsigned pack_bf16(float lo, float hi) {
    unsigned d;
    asm("cvt.rn.bf16x2.f32 %0, %1, %2;" : "=r"(d) : "f"(hi), "f"(lo));
    return d;
}

__device__ __forceinline__ void mma_bf16(float (&d)[4],
                                         const unsigned (&a)[4],
                                         const unsigned b0, const unsigned b1) {
    asm volatile(
        "mma.sync.aligned.m16n8k16.row.col.f32.bf16.bf16.f32 "
        "{%0,%1,%2,%3}, {%4,%5,%6,%7}, {%8,%9}, {%0,%1,%2,%3};\n"
        : "+f"(d[0]), "+f"(d[1]), "+f"(d[2]), "+f"(d[3])
        : "r"(a[0]), "r"(a[1]), "r"(a[2]), "r"(a[3]),
          "r"(b0), "r"(b1));
}

__device__ __forceinline__ void ldsm_x4(unsigned& r0, unsigned& r1,
                                        unsigned& r2, unsigned& r3,
                                        uint32_t addr) {
    asm volatile("ldmatrix.sync.aligned.m8n8.x4.shared.b16 {%0,%1,%2,%3}, [%4];"
                 : "=r"(r0), "=r"(r1), "=r"(r2), "=r"(r3) : "r"(addr));
}

#define CP_ASYNC16(dst, src) \
    asm volatile("cp.async.cg.shared.global [%0], [%1], 16;\n" :: "r"(dst), "l"(src))
#define CP_COMMIT() asm volatile("cp.async.commit_group;\n")
#define CP_WAIT(n)  asm volatile("cp.async.wait_group %0;\n" :: "n"(n))

// Geometry: K-chunk 32.
// B (bf16, cp.async, 3 stages): 256 rows x 16 words + 4 pad = 20 words/row.
// A (bf16, LDG->cvt->STS, 2 buffers): 64 rows x 20 words/row.
#define B_ROWW 20
#define B_ST_WORDS (256 * B_ROWW)            // 5120 words / stage
#define B_TOTAL_WORDS (3 * B_ST_WORDS)       // 15360
#define A_ROWW 20
#define A_BUF_WORDS (64 * A_ROWW)            // 1280 words / buffer
#define DYN_SMEM_BYTES ((B_TOTAL_WORDS + 2 * A_BUF_WORDS) * 4)   // 71680

// ---------------------------------------------------------------------------
// prep: W1 [D][H] f32 -> g_W1T [H][D] bf16 ; zero out[0]
// ---------------------------------------------------------------------------
__global__ void prep_kernel(const float* __restrict__ W1, float* out) {
    __shared__ float tile[32][33];
    const int k0 = blockIdx.x * 32;
    const int n0 = blockIdx.y * 32;
    if (blockIdx.x == 0 && blockIdx.y == 0 && threadIdx.x == 0 && threadIdx.y == 0)
        out[0] = 0.0f;
    tile[threadIdx.y][threadIdx.x] = W1[(size_t)(k0 + threadIdx.y) * HH + n0 + threadIdx.x];
    __syncthreads();
    g_W1T[(size_t)(n0 + threadIdx.y) * DD + k0 + threadIdx.x] =
        __float2bfloat16(tile[threadIdx.x][threadIdx.y]);
}

// ---------------------------------------------------------------------------
// Kernel 1: fused  em = gelu(x @ W1 + b1) @ W2 + b2   via bf16 m16n8k16.
// Block 256 thr (8 warps), BM=64, BN=256, BK=32.
// All fragments loaded via ldmatrix.x4 (12 LDSM/chunk/warp vs 32 LDS.32).
// ---------------------------------------------------------------------------
__global__ __launch_bounds__(256, 2)
void fused_mlp_bf16(const float* __restrict__ x,
                    const float* __restrict__ b1,
                    const float* __restrict__ W2,
                    const float* __restrict__ b2)
{
    extern __shared__ uint32_t dsm[];
    uint32_t* bsm = dsm;                      // B stages: 3 x 5120 words
    uint32_t* asm0 = dsm + B_TOTAL_WORDS;     // A buffer 0
    uint32_t* asm1 = asm0 + A_BUF_WORDS;      // A buffer 1

    __shared__ float s_w2[256][3];
    __shared__ float s_b1[256];
    __shared__ float em_s[64][3];

    const int tid  = threadIdx.x;
    const int wid  = tid >> 5;
    const int lane = tid & 31;
    const int g    = lane >> 2;
    const int c    = lane & 3;
    const int row_base = blockIdx.x * 64;
    const int cw   = wid * 32;

    s_b1[tid]    = b1[tid];
    s_w2[tid][0] = W2[tid * 3 + 0];
    s_w2[tid][1] = W2[tid * 3 + 1];
    s_w2[tid][2] = W2[tid * 3 + 2];
    if (tid < 192) ((float*)em_s)[tid] = 0.0f;

    // per-lane ldmatrix address offsets (in words)
    const int lm  = lane >> 3;    // matrix id 0..3
    const int lr  = lane & 7;     // row within matrix
    const int aoff = ((lm & 1) * 8 + lr) * A_ROWW + (lm >> 1) * 4;
    const int boff = ((lm >> 1) * 8 + lr) * B_ROWW + (lm & 1) * 4;

    const uint32_t a0_sm = (uint32_t)__cvta_generic_to_shared(asm0) + aoff * 4;
    const uint32_t a1_sm = (uint32_t)__cvta_generic_to_shared(asm1) + aoff * 4;
    const uint32_t b_sm  = (uint32_t)__cvta_generic_to_shared(bsm) +
                           (cw * B_ROWW + boff) * 4;

    float acc[4][4][4];
    #pragma unroll
    for (int mt = 0; mt < 4; ++mt)
        #pragma unroll
        for (int nt = 0; nt < 4; ++nt)
            #pragma unroll
            for (int e = 0; e < 4; ++e) acc[mt][nt][e] = 0.0f;

    // ---- A chunk loader (LDG f32 -> regs -> cvt -> STS bf16) ----
    const int ar0 = tid >> 3,           ach0 = tid & 7;
    const int ar1 = (tid + 256) >> 3,   ach1 = (tid + 256) & 7;
    auto ldgA = [&](float4& v0, float4& v1, int k0) {
        v0 = *(const float4*)&x[(size_t)(row_base + ar0) * DD + k0 + ach0 * 4];
        v1 = *(const float4*)&x[(size_t)(row_base + ar1) * DD + k0 + ach1 * 4];
    };
    auto stsA = [&](uint32_t* abuf, const float4& v0, const float4& v1) {
        uint2 w0 = make_uint2(pack_bf16(v0.x, v0.y), pack_bf16(v0.z, v0.w));
        uint2 w1 = make_uint2(pack_bf16(v1.x, v1.y), pack_bf16(v1.z, v1.w));
        *(uint2*)&abuf[ar0 * A_ROWW + ach0 * 2] = w0;
        *(uint2*)&abuf[ar1 * A_ROWW + ach1 * 2] = w1;
    };

    // ---- B stage loader ----
    auto issueB = [&](int s, int k0) {
        const uint32_t base = (uint32_t)__cvta_generic_to_shared(bsm) + s * (B_ST_WORDS * 4);
        #pragma unroll
        for (int i = 0; i < 4; ++i) {
            const int id = tid + i * 256;
            const int n = id >> 2, j = id & 3;
            CP_ASYNC16(base + n * (B_ROWW * 4) + j * 16,
                       &g_W1T[(size_t)n * DD + k0 + j * 8]);
        }
        CP_COMMIT();
    };

    // ---- compute one chunk: A buffer addr + B stage index ----
    auto compute = [&](uint32_t a_base, int bstage) {
        const uint32_t bb = b_sm + bstage * (B_ST_WORDS * 4);
        #pragma unroll
        for (int ks = 0; ks < 2; ++ks) {
            const uint32_t kw4 = ks * 8 * 4;
            unsigned bf[4][2];
            ldsm_x4(bf[0][0], bf[0][1], bf[1][0], bf[1][1], bb + kw4);
            ldsm_x4(bf[2][0], bf[2][1], bf[3][0], bf[3][1],
                    bb + 16 * (B_ROWW * 4) + kw4);
            #pragma unroll
            for (int mt = 0; mt < 4; ++mt) {
                unsigned af[4];
                ldsm_x4(af[0], af[1], af[2], af[3],
                        a_base + mt * 16 * (A_ROWW * 4) + kw4);
                #pragma unroll
                for (int nt = 0; nt < 4; ++nt)
                    mma_bf16(acc[mt][nt], af, bf[nt][0], bf[nt][1]);
            }
        }
    };

    // ---- prologue ----
    float4 raA0, raA1, raB0, raB1;
    ldgA(raA0, raA1, 0);
    stsA(asm0, raA0, raA1);
    issueB(0, 0);
    issueB(1, 32);
    ldgA(raA0, raA1, 32);

    const int NST = DD / 32;   // 16 chunks, unrolled x2 (static reg ping-pong)
    #pragma unroll 1
    for (int it = 0; it < NST; it += 2) {
        CP_WAIT(1);
        __syncthreads();
        stsA(asm1, raA0, raA1);
        if (it + 2 < NST) { ldgA(raB0, raB1, (it + 2) * 32); issueB((it + 2) % 3, (it + 2) * 32); }
        compute(a0_sm, it % 3);

        if (it + 1 == NST - 1) { CP_WAIT(0); } else { CP_WAIT(1); }
        __syncthreads();
        stsA(asm0, raB0, raB1);
        if (it + 3 < NST) { ldgA(raA0, raA1, (it + 3) * 32); issueB((it + 3) % 3, (it + 3) * 32); }
        compute(a1_sm, (it + 1) % 3);
    }

    // ---- epilogue: bias + exact gelu + W2 contraction ----
    float pem[8][3];
    #pragma unroll
    for (int i = 0; i < 8; ++i)
        #pragma unroll
        for (int k = 0; k < 3; ++k) pem[i][k] = 0.0f;

    #pragma unroll
    for (int mt = 0; mt < 4; ++mt)
        #pragma unroll
        for (int nt = 0; nt < 4; ++nt)
            #pragma unroll
            for (int e = 0; e < 4; ++e) {
                const int col = cw + nt * 8 + 2 * c + (e & 1);
                const int slot = mt * 2 + (e >> 1);
                const float v = acc[mt][nt][e] + s_b1[col];
                const float h = 0.5f * v * (1.0f + erff(v * 0.7071067811865476f));
                pem[slot][0] = fmaf(h, s_w2[col][0], pem[slot][0]);
                pem[slot][1] = fmaf(h, s_w2[col][1], pem[slot][1]);
                pem[slot][2] = fmaf(h, s_w2[col][2], pem[slot][2]);
            }

    #pragma unroll
    for (int d = 1; d < 4; d <<= 1)
        #pragma unroll
        for (int i = 0; i < 8; ++i)
            #pragma unroll
            for (int k = 0; k < 3; ++k)
                pem[i][k] += __shfl_xor_sync(0xffffffffu, pem[i][k], d);

    if (c == 0) {
        #pragma unroll
        for (int i = 0; i < 8; ++i) {
            const int row = (i >> 1) * 16 + g + (i & 1) * 8;
            atomicAdd(&em_s[row][0], pem[i][0]);
            atomicAdd(&em_s[row][1], pem[i][1]);
            atomicAdd(&em_s[row][2], pem[i][2]);
        }
    }
    __syncthreads();

    if (tid < 192) {
        g_em[(size_t)row_base * 3 + tid] = ((float*)em_s)[tid] + b2[tid % 3];
    }
}

// ---------------------------------------------------------------------------
// Kernel 2: CRF via log-semiring associative scan (unchanged, proven 12us).
// ---------------------------------------------------------------------------
__device__ __forceinline__ float sel3(float a, float b, float c, int i) {
    return (i == 0) ? a : ((i == 1) ? b : c);
}
__device__ __forceinline__ float lse3(float x, float y, float z) {
    const float m = fmaxf(fmaxf(x, y), z);
    return m + __logf(__expf(x - m) + __expf(y - m) + __expf(z - m));
}

#define CRF_WARPS 4

__global__ __launch_bounds__(32 * CRF_WARPS)
void crf_kernel(const int* __restrict__ tags,
                const int* __restrict__ lengths,
                const float* __restrict__ trans,
                const float* __restrict__ start,
                const float* __restrict__ end,
                float* __restrict__ out)
{
    __shared__ float s_em[CRF_WARPS][TT * 3];
    __shared__ int   s_tag[CRF_WARPS][TT];
    __shared__ float s_tr[9];

    const int wid  = threadIdx.x >> 5;
    const int lane = threadIdx.x & 31;
    const int b    = blockIdx.x * CRF_WARPS + wid;

    if (threadIdx.x < 9) s_tr[threadIdx.x] = trans[threadIdx.x];
    __syncthreads();

    {
        const float4* src = reinterpret_cast<const float4*>(&g_em[(size_t)b * TT * 3]);
        float4* dst = reinterpret_cast<float4*>(s_em[wid]);
        #pragma unroll
        for (int i = 0; i < 12; ++i) dst[lane + i * 32] = src[lane + i * 32];
        const int4* ts = reinterpret_cast<const int4*>(&tags[(size_t)b * TT]);
        int4* td = reinterpret_cast<int4*>(s_tag[wid]);
        #pragma unroll
        for (int i = 0; i < 4; ++i) td[lane + i * 32] = ts[lane + i * 32];
    }
    __syncwarp();

    const float t00 = s_tr[0], t01 = s_tr[1], t02 = s_tr[2];
    const float t10 = s_tr[3], t11 = s_tr[4], t12 = s_tr[5];
    const float t20 = s_tr[6], t21 = s_tr[7], t22 = s_tr[8];
    const float st0 = start[0], st1 = start[1], st2 = start[2];
    const float en0 = end[0],   en1 = end[1],   en2 = end[2];

    const int len = max(lengths[b], 1);
    const float* em = s_em[wid];
    const int*   tg = s_tag[wid];

    const int t0 = 1 + lane * 16;
    float M[3][3];
    if (t0 < len) {
        float e0 = em[t0 * 3 + 0], e1 = em[t0 * 3 + 1], e2 = em[t0 * 3 + 2];
        M[0][0] = t00 + e0; M[0][1] = t01 + e1; M[0][2] = t02 + e2;
        M[1][0] = t10 + e0; M[1][1] = t11 + e1; M[1][2] = t12 + e2;
        M[2][0] = t20 + e0; M[2][1] = t21 + e1; M[2][2] = t22 + e2;
        #pragma unroll 1
        for (int s = 1; s < 16; ++s) {
            const int t = t0 + s;
            if (t >= len) break;
            e0 = em[t * 3 + 0]; e1 = em[t * 3 + 1]; e2 = em[t * 3 + 2];
            float C[3][3];
            #pragma unroll
            for (int i = 0; i < 3; ++i) {
                C[i][0] = lse3(M[i][0] + t00, M[i][1] + t10, M[i][2] + t20) + e0;
                C[i][1] = lse3(M[i][0] + t01, M[i][1] + t11, M[i][2] + t21) + e1;
                C[i][2] = lse3(M[i][0] + t02, M[i][1] + t12, M[i][2] + t22) + e2;
            }
            #pragma unroll
            for (int i = 0; i < 3; ++i)
                #pragma unroll
                for (int k = 0; k < 3; ++k) M[i][k] = C[i][k];
        }
    } else {
        #pragma unroll
        for (int i = 0; i < 3; ++i)
            #pragma unroll
            for (int k = 0; k < 3; ++k) M[i][k] = (i == k) ? 0.0f : NEG;
    }

    float num = 0.0f;
    {
        int tp = tg[t0 - 1];
        #pragma unroll 1
        for (int s = 0; s < 16; ++s) {
            const int t = t0 + s;
            if (t >= len) break;
            const int tc = tg[t];
            num += s_tr[tp * 3 + tc] + em[t * 3 + tc];
            tp = tc;
        }
    }
    if (lane == 0) {
        const int tag0 = tg[0];
        num += sel3(st0, st1, st2, tag0) + sel3(em[0], em[1], em[2], tag0);
        if (len == 1) num += sel3(en0, en1, en2, tag0);
    }
    {
        const int tl = len - 1;
        if (tl >= t0 && tl < t0 + 16) num += sel3(en0, en1, en2, tg[tl]);
    }

    #pragma unroll
    for (int off = 1; off < 32; off <<= 1) {
        float O[3][3];
        #pragma unroll
        for (int i = 0; i < 3; ++i)
            #pragma unroll
            for (int k = 0; k < 3; ++k)
                O[i][k] = __shfl_xor_sync(0xffffffffu, M[i][k], off);
        const bool lower = ((lane & off) == 0);
        float L[3][3], R[3][3];
        #pragma unroll
        for (int i = 0; i < 3; ++i)
            #pragma unroll
            for (int k = 0; k < 3; ++k) {
                L[i][k] = lower ? M[i][k] : O[i][k];
                R[i][k] = lower ? O[i][k] : M[i][k];
            }
        #pragma unroll
        for (int i = 0; i < 3; ++i)
            #pragma unroll
            for (int k = 0; k < 3; ++k)
                M[i][k] = lse3(L[i][0] + R[0][k], L[i][1] + R[1][k], L[i][2] + R[2][k]);
    }

    #pragma unroll
    for (int off = 16; off > 0; off >>= 1)
        num += __shfl_xor_sync(0xffffffffu, num, off);

    if (lane == 0) {
        const float a00 = st0 + em[0];
        const float a01 = st1 + em[1];
        const float a02 = st2 + em[2];
        float aT[3];
        #pragma unroll
        for (int k = 0; k < 3; ++k)
            aT[k] = lse3(a00 + M[0][k], a01 + M[1][k], a02 + M[2][k]);
        const float denom = lse3(aT[0] + en0, aT[1] + en1, aT[2] + en2);
        atomicAdd(out, -(num - denom) * (1.0f / (float)BB));
    }
}

// ---------------------------------------------------------------------------
extern "C" void kernel_launch(void* const* d_in, const int* in_sizes, int n_in,
                              void* d_out, int out_size)
{
    const float* x       = (const float*)d_in[0];
    const int*   tags    = (const int*)  d_in[1];
    const int*   lengths = (const int*)  d_in[2];
    const float* W1      = (const float*)d_in[3];
    const float* b1      = (const float*)d_in[4];
    const float* W2      = (const float*)d_in[5];
    const float* b2      = (const float*)d_in[6];
    const float* trans   = (const float*)d_in[7];
    const float* start   = (const float*)d_in[8];
    const float* end     = (const float*)d_in[9];

    cudaFuncSetAttribute(fused_mlp_bf16,
                         cudaFuncAttributeMaxDynamicSharedMemorySize,
                         DYN_SMEM_BYTES);

    prep_kernel<<<dim3(DD / 32, HH / 32), dim3(32, 32)>>>(W1, (float*)d_out);
    fused_mlp_bf16<<<MM / 64, 256, DYN_SMEM_BYTES>>>(x, b1, W2, b2);
    crf_kernel<<<BB / CRF_WARPS, 32 * CRF_WARPS>>>(tags, lengths, trans, start, end,
                                                   (float*)d_out);
}